// round 10
// baseline (speedup 1.0000x reference)
#include <cuda_runtime.h>
#include <cuda_bf16.h>
#include <math.h>
#include <stdint.h>

// ---------------- problem constants ----------------
constexpr int NCOL = 256;
constexpr int PNUM = 4096;
constexpr int ROWS = 32768;
constexpr int TM   = 64;      // M rows per CTA
constexpr int KT   = 64;      // K tile (doubled vs R9)

__host__ __device__ constexpr int W1OFF(int s) {
    return s == 0 ? 0 : (s == 1 ? 98304 : 229376);
}
__host__ __device__ constexpr int W2OFF(int s) {
    return s == 0 ? 32768 : (s == 1 ? 163840 : 360448);
}
constexpr int WTOTAL = 425984;

__device__ uint4 g_whi4[WTOTAL / 8];   // transposed [n][k] bf16 hi, 64-k tiles
__device__ uint4 g_wlo4[WTOTAL / 8];   // lo residuals

// ---------------- smem word offsets ----------------
// h region: 64 x 132 words hi @0, lo @8448.
// A tile (64 x 36 hi + lo) ALIASES the h-hi region (GEMM1 only; h written at
// the GEMM1->GEMM2 boundary behind a barrier).
constexpr int O_SHH = 0;
constexpr int O_SHL = 8448;
constexpr int O_SXH = 0;          // alias
constexpr int O_SXL = 4224;       // alias (2304 words needed, fits in 8448)
constexpr int O_W   = 16896;      // 2 bufs x (hi 9216 + lo 9216) = 36864
constexpr int WBUF  = 18432;      // words per buffer
constexpr int O_SB1 = 53760;
constexpr int O_SB2 = 54016;
constexpr int O_SSP = 54272;
constexpr int O_PID = 54528;
constexpr int SMEM_WORDS = 54592;
constexpr int SMEM_BYTES = SMEM_WORDS * 4;   // 218,368 B (<= 227 KB)

struct Params {
    const float* feat[3];
    const int*   pid[3];
    const float* w1[3];
    const float* b1[3];
    const float* w2[3];
    const float* b2[3];
    float*       out;
};

__device__ __forceinline__ uint32_t s2u(const void* p) {
    uint32_t a;
    asm("{ .reg .u64 t; cvta.to.shared.u64 t, %1; cvt.u32.u64 %0, t; }" : "=r"(a) : "l"(p));
    return a;
}
__device__ __forceinline__ void cp16(uint32_t saddr, const void* g) {
    asm volatile("cp.async.cg.shared.global [%0], [%1], 16;" :: "r"(saddr), "l"(g));
}
#define CP_COMMIT() asm volatile("cp.async.commit_group;" ::: "memory")
#define CP_WAIT0()  asm volatile("cp.async.wait_group 0;" ::: "memory")

__device__ __forceinline__ uint32_t pack_bf2(__nv_bfloat16 lo, __nv_bfloat16 hi) {
    return (uint32_t)__bfloat16_as_ushort(hi) << 16 | (uint32_t)__bfloat16_as_ushort(lo);
}
__device__ __forceinline__ void split2(float v0, float v1, uint32_t& hw, uint32_t& lw) {
    __nv_bfloat16 h0 = __float2bfloat16(v0);
    __nv_bfloat16 h1 = __float2bfloat16(v1);
    __nv_bfloat16 l0 = __float2bfloat16(v0 - __bfloat162float(h0));
    __nv_bfloat16 l1 = __float2bfloat16(v1 - __bfloat162float(h1));
    hw = pack_bf2(h0, h1);
    lw = pack_bf2(l0, l1);
}
__device__ __forceinline__ void mma16816(float* d, const uint32_t* a,
                                         uint32_t b0, uint32_t b1) {
    asm volatile(
        "mma.sync.aligned.m16n8k16.row.col.f32.bf16.bf16.f32 "
        "{%0,%1,%2,%3}, {%4,%5,%6,%7}, {%8,%9}, {%0,%1,%2,%3};"
        : "+f"(d[0]), "+f"(d[1]), "+f"(d[2]), "+f"(d[3])
        : "r"(a[0]), "r"(a[1]), "r"(a[2]), "r"(a[3]), "r"(b0), "r"(b1));
}
#define LDMX4(r0, r1, r2, r3, addr)                                           \
    asm volatile("ldmatrix.sync.aligned.m8n8.x4.shared.b16 {%0,%1,%2,%3}, [%4];" \
        : "=r"(r0), "=r"(r1), "=r"(r2), "=r"(r3) : "r"(addr))

// ---------------- weight prep: 64-k tiles, [n][k] bf16 hi/lo ----------------
__global__ void prep_weights(Params P)
{
    __nv_bfloat16* ghi = (__nv_bfloat16*)g_whi4;
    __nv_bfloat16* glo = (__nv_bfloat16*)g_wlo4;
    for (int m = 0; m < 6; m++) {
        int s = m >> 1;
        bool isw2 = m & 1;
        const float* w = isw2 ? P.w2[s] : P.w1[s];
        int K   = isw2 ? 256 : (128 << s);
        int off = isw2 ? W2OFF(s) : W1OFF(s);
        int nel = K * 256;
        for (int e = blockIdx.x * blockDim.x + threadIdx.x; e < nel;
             e += gridDim.x * blockDim.x) {
            int k = e >> 8, n = e & 255;
            float v = w[e];
            __nv_bfloat16 hi = __float2bfloat16(v);
            __nv_bfloat16 lo = __float2bfloat16(v - __bfloat162float(hi));
            int d = off + (k >> 6) * 16384 + n * 64 + (k & 63);
            ghi[d] = hi;
            glo[d] = lo;
        }
    }
}

// ---------------- fused kernel ----------------
__global__ void __launch_bounds__(512, 1)
fused_mma(Params P)
{
    extern __shared__ uint32_t smw[];
    uint32_t* sxh = smw + O_SXH;
    uint32_t* sxl = smw + O_SXL;
    float*    sb1 = (float*)(smw + O_SB1);
    float*    sb2 = (float*)(smw + O_SB2);
    float*    ssp = (float*)(smw + O_SSP);
    int*      spid = (int*)(smw + O_PID);
    const uint32_t smb = s2u(smw);

    const int tid  = threadIdx.x;
    const int lane = tid & 31;
    const int wid  = tid >> 5;
    const int wm   = wid & 3;          // rows wm*16..+15
    const int wn   = wid >> 2;         // cols wn*64..+63
    const int gr   = lane >> 2;
    const int c    = lane & 3;
    const int rowA = wm * 16 + gr;
    const int lr   = lane & 15;
    const int lh   = lane >> 4;

    const int s  = blockIdx.x % 3;
    const int bi = blockIdx.x / 3;
    const int C  = 128 << s;
    const int HW = 32768 >> (2 * s);
    const int NT1 = C / KT;            // 2 / 4 / 8
    const int T   = NT1 + 4;

    const float* __restrict__ feat = P.feat[s];
    const int*   __restrict__ pid  = P.pid[s];

    const int row0 = bi * TM;
    const int b    = row0 >> 12;
    const int p0   = row0 & (PNUM - 1);

    if (tid < TM)  spid[tid] = pid[b * PNUM + p0 + tid];
    if (tid < 256) { sb1[tid] = __ldg(&P.b1[s][tid]); sb2[tid] = __ldg(&P.b2[s][tid]); }
    __syncthreads();

    const float* featb = feat + (size_t)b * C * HW;
    const __nv_bfloat16* ghi = (const __nv_bfloat16*)g_whi4;
    const __nv_bfloat16* glo = (const __nv_bfloat16*)g_wlo4;

    // gather mapping: thread -> row gr0, k-pairs {gkp, gkp+8, gkp+16, gkp+24}
    const int gr0 = tid & 63;
    const int gkp = tid >> 6;          // 0..7
    const int mypid = spid[gr0];

    float acc[8][4];
#pragma unroll
    for (int nt = 0; nt < 8; nt++)
#pragma unroll
        for (int q = 0; q < 4; q++) acc[nt][q] = 0.f;

    float va[8];                       // A gather prefetch (4 k-pairs)

    // W cp.async issue helper (2048 uint4 hi + 2048 lo per tile)
    auto issueW = [&](int t) {
        const int woff = (t < NT1) ? (W1OFF(s) + t * 16384)
                                   : (W2OFF(s) + (t - NT1) * 16384);
        const char* srch = (const char*)(ghi + woff);
        const char* srcl = (const char*)(glo + woff);
        const uint32_t wh = smb + (O_W + (t & 1) * WBUF) * 4;
        const uint32_t wl = wh + 9216 * 4;
#pragma unroll
        for (int j = 0; j < 4; j++) {
            int u = tid + j * 512;
            uint32_t doff = (u >> 3) * 144 + (u & 7) * 16;
            cp16(wh + doff, srch + (size_t)u * 16);
            cp16(wl + doff, srcl + (size_t)u * 16);
        }
        CP_COMMIT();
    };
    auto gatherA = [&](int t) {
#pragma unroll
        for (int j = 0; j < 4; j++) {
            int k = t * KT + (gkp + 8 * j) * 2;
            va[2 * j]     = __ldg(&featb[(size_t)k * HW + mypid]);
            va[2 * j + 1] = __ldg(&featb[(size_t)(k + 1) * HW + mypid]);
        }
    };

    // ---- prologue ----
    issueW(0);
    gatherA(0);

    // ldmatrix base addresses (bytes)
    const uint32_t adrA1_h = smb + (O_SXH + (wm * 16 + lr) * 36 + lh * 4) * 4;
    const uint32_t adrA1_l = smb + (O_SXL + (wm * 16 + lr) * 36 + lh * 4) * 4;
    const uint32_t adrA2_h = smb + (O_SHH + (wm * 16 + lr) * 132 + lh * 4) * 4;
    const uint32_t adrA2_l = smb + (O_SHL + (wm * 16 + lr) * 132 + lh * 4) * 4;

    for (int t = 0; t < T; t++) {
        // ---- GEMM1->GEMM2 boundary: write h (aliases A; loop-end sync of t-1
        //      guarantees every warp finished its GEMM1 MMA reads of A) ----
        if (t == NT1) {
            uint32_t* shh = smw + O_SHH;
            uint32_t* shl = smw + O_SHL;
#pragma unroll
            for (int nt = 0; nt < 8; nt++) {
                const int n  = wn * 64 + nt * 8 + 2 * c;
                const int wi = wn * 32 + nt * 4 + c;
                float v0 = fmaxf(acc[nt][0] + sb1[n],     0.f);
                float v1 = fmaxf(acc[nt][1] + sb1[n + 1], 0.f);
                float v2 = fmaxf(acc[nt][2] + sb1[n],     0.f);
                float v3 = fmaxf(acc[nt][3] + sb1[n + 1], 0.f);
                uint32_t hw, lw;
                split2(v0, v1, hw, lw);
                shh[rowA * 132 + wi] = hw;
                shl[rowA * 132 + wi] = lw;
                split2(v2, v3, hw, lw);
                shh[(rowA + 8) * 132 + wi] = hw;
                shl[(rowA + 8) * 132 + wi] = lw;
#pragma unroll
                for (int q = 0; q < 4; q++) acc[nt][q] = 0.f;
            }
        }
        // ---- store gathered A for this tile ----
        if (t < NT1) {
#pragma unroll
            for (int j = 0; j < 4; j++) {
                uint32_t hw, lw;
                split2(va[2 * j], va[2 * j + 1], hw, lw);
                sxh[gr0 * 36 + gkp + 8 * j] = hw;
                sxl[gr0 * 36 + gkp + 8 * j] = lw;
            }
        }
        CP_WAIT0();           // W(t) landed
        __syncthreads();

        // ---- issue W(t+1) + gather va(t+1); both overlap the MMA below ----
        if (t + 1 < T) issueW(t + 1);
        if (t + 1 < NT1) gatherA(t + 1);

        // ---- MMA phase on W buffer t&1 ----
        const uint32_t adrB_h = smb + (O_W + (t & 1) * WBUF + (wn * 64 + lr) * 36 + lh * 4) * 4;
        const uint32_t adrB_l = adrB_h + 9216 * 4;
#pragma unroll
        for (int ks = 0; ks < 4; ks++) {
            uint32_t ah[4], al[4];
            if (t < NT1) {
                LDMX4(ah[0], ah[1], ah[2], ah[3], adrA1_h + ks * 32);
                LDMX4(al[0], al[1], al[2], al[3], adrA1_l + ks * 32);
            } else {
                const uint32_t koff = (uint32_t)(t - NT1) * 128 + ks * 32;
                LDMX4(ah[0], ah[1], ah[2], ah[3], adrA2_h + koff);
                LDMX4(al[0], al[1], al[2], al[3], adrA2_l + koff);
            }
#pragma unroll
            for (int p = 0; p < 4; p++) {
                uint32_t bh[4], bl[4];
                const uint32_t boff = (uint32_t)p * 16 * 144 + ks * 32;
                LDMX4(bh[0], bh[1], bh[2], bh[3], adrB_h + boff);
                LDMX4(bl[0], bl[1], bl[2], bl[3], adrB_l + boff);
                mma16816(acc[2 * p],     ah, bh[0], bh[2]);
                mma16816(acc[2 * p],     ah, bl[0], bl[2]);
                mma16816(acc[2 * p],     al, bh[0], bh[2]);
                mma16816(acc[2 * p + 1], ah, bh[1], bh[3]);
                mma16816(acc[2 * p + 1], ah, bl[1], bl[3]);
                mma16816(acc[2 * p + 1], al, bh[1], bh[3]);
            }
        }
        __syncthreads();
    }

    // ================= epilogue: +b2, L2 normalize, store =================
    float ss0 = 0.f, ss1 = 0.f;
#pragma unroll
    for (int nt = 0; nt < 8; nt++) {
        const int n = wn * 64 + nt * 8 + 2 * c;
        acc[nt][0] += sb2[n];
        acc[nt][1] += sb2[n + 1];
        acc[nt][2] += sb2[n];
        acc[nt][3] += sb2[n + 1];
        ss0 = fmaf(acc[nt][0], acc[nt][0], fmaf(acc[nt][1], acc[nt][1], ss0));
        ss1 = fmaf(acc[nt][2], acc[nt][2], fmaf(acc[nt][3], acc[nt][3], ss1));
    }
    ss0 += __shfl_xor_sync(0xffffffffu, ss0, 1);
    ss0 += __shfl_xor_sync(0xffffffffu, ss0, 2);
    ss1 += __shfl_xor_sync(0xffffffffu, ss1, 1);
    ss1 += __shfl_xor_sync(0xffffffffu, ss1, 2);
    if (c == 0) {
        ssp[rowA * 4 + wn]       = ss0;
        ssp[(rowA + 8) * 4 + wn] = ss1;
    }
    __syncthreads();
    const float inv0 = 1.f / (sqrtf(ssp[rowA * 4] + ssp[rowA * 4 + 1] +
                                    ssp[rowA * 4 + 2] + ssp[rowA * 4 + 3]) + 1e-7f);
    const float inv1 = 1.f / (sqrtf(ssp[(rowA + 8) * 4] + ssp[(rowA + 8) * 4 + 1] +
                                    ssp[(rowA + 8) * 4 + 2] + ssp[(rowA + 8) * 4 + 3]) + 1e-7f);

    float* __restrict__ out = P.out + ((size_t)s * ROWS + row0) * NCOL;
#pragma unroll
    for (int nt = 0; nt < 8; nt++) {
        const int n = wn * 64 + nt * 8 + 2 * c;
        float2 o0 = make_float2(acc[nt][0] * inv0, acc[nt][1] * inv0);
        float2 o1 = make_float2(acc[nt][2] * inv1, acc[nt][3] * inv1);
        *(float2*)&out[(size_t)rowA * NCOL + n]       = o0;
        *(float2*)&out[(size_t)(rowA + 8) * NCOL + n] = o1;
    }
}

// ---------------- launch ----------------
extern "C" void kernel_launch(void* const* d_in, const int* in_sizes, int n_in,
                              void* d_out, int out_size)
{
    const bool sig_order = (n_in > 1) && (in_sizes[1] == 16777216);

    Params P;
    if (sig_order) {
        for (int s = 0; s < 3; s++) {
            P.feat[s] = (const float*)d_in[s];
            P.pid[s]  = (const int*)  d_in[3 + s];
            P.w1[s]   = (const float*)d_in[6 + 4 * s];
            P.b1[s]   = (const float*)d_in[7 + 4 * s];
            P.w2[s]   = (const float*)d_in[8 + 4 * s];
            P.b2[s]   = (const float*)d_in[9 + 4 * s];
        }
    } else {
        for (int s = 0; s < 3; s++) {
            P.feat[s] = (const float*)d_in[6 * s + 0];
            P.pid[s]  = (const int*)  d_in[6 * s + 1];
            P.w1[s]   = (const float*)d_in[6 * s + 2];
            P.b1[s]   = (const float*)d_in[6 * s + 3];
            P.w2[s]   = (const float*)d_in[6 * s + 4];
            P.b2[s]   = (const float*)d_in[6 * s + 5];
        }
    }
    P.out = (float*)d_out;

    cudaFuncSetAttribute(fused_mma, cudaFuncAttributeMaxDynamicSharedMemorySize,
                         SMEM_BYTES);

    prep_weights<<<256, 256>>>(P);
    fused_mma<<<3 * (ROWS / TM), 512, SMEM_BYTES>>>(P);
}

// round 11
// speedup vs baseline: 1.3703x; 1.3703x over previous
#include <cuda_runtime.h>
#include <cuda_bf16.h>
#include <math.h>
#include <stdint.h>

// ---------------- problem constants ----------------
constexpr int NCOL = 256;
constexpr int PNUM = 4096;
constexpr int ROWS = 32768;
constexpr int TM   = 64;      // M rows per CTA
constexpr int KT   = 32;      // K tile

__host__ __device__ constexpr int W1OFF(int s) {
    return s == 0 ? 0 : (s == 1 ? 98304 : 229376);
}
__host__ __device__ constexpr int W2OFF(int s) {
    return s == 0 ? 32768 : (s == 1 ? 163840 : 360448);
}
constexpr int WTOTAL = 425984;

// transposed-feat scratch (bf16 elem offsets): s1 @0 (8*8192*256), s2 @16777216
__host__ __device__ constexpr size_t TOFF(int s) {
    return s == 1 ? 0 : 16777216;
}
constexpr size_t TTOTAL = 25165824;   // bf16 elems per plane

__device__ uint4 g_whi4[WTOTAL / 8];
__device__ uint4 g_wlo4[WTOTAL / 8];
__device__ uint4 g_thi4[TTOTAL / 8];  // feat^T bf16 hi plane (s1, s2)
__device__ uint4 g_tlo4[TTOTAL / 8];  // lo plane

// ---------------- smem word offsets (same as R9) ----------------
constexpr int O_SXH = 0;          // A hi: 64 x 20 words
constexpr int O_SXL = 1280;
constexpr int O_SWH = 2560;       // W hi: 256 x 20 words
constexpr int O_SWL = 7680;
constexpr int O_SHH = 12800;      // h hi: 64 x 132 words
constexpr int O_SHL = 21248;
constexpr int O_SB1 = 29696;
constexpr int O_SB2 = 29952;
constexpr int O_SSP = 30208;
constexpr int O_PID = 30464;
constexpr int SMEM_WORDS = 30528;
constexpr int SMEM_BYTES = SMEM_WORDS * 4;   // 122,112 B

struct Params {
    const float* feat[3];
    const int*   pid[3];
    const float* w1[3];
    const float* b1[3];
    const float* w2[3];
    const float* b2[3];
    float*       out;
};

__device__ __forceinline__ uint32_t s2u(const void* p) {
    uint32_t a;
    asm("{ .reg .u64 t; cvta.to.shared.u64 t, %1; cvt.u32.u64 %0, t; }" : "=r"(a) : "l"(p));
    return a;
}
__device__ __forceinline__ uint32_t pack_bf2(__nv_bfloat16 lo, __nv_bfloat16 hi) {
    return (uint32_t)__bfloat16_as_ushort(hi) << 16 | (uint32_t)__bfloat16_as_ushort(lo);
}
__device__ __forceinline__ void split2(float v0, float v1, uint32_t& hw, uint32_t& lw) {
    __nv_bfloat16 h0 = __float2bfloat16(v0);
    __nv_bfloat16 h1 = __float2bfloat16(v1);
    __nv_bfloat16 l0 = __float2bfloat16(v0 - __bfloat162float(h0));
    __nv_bfloat16 l1 = __float2bfloat16(v1 - __bfloat162float(h1));
    hw = pack_bf2(h0, h1);
    lw = pack_bf2(l0, l1);
}
__device__ __forceinline__ void mma16816(float* d, const uint32_t* a,
                                         uint32_t b0, uint32_t b1) {
    asm volatile(
        "mma.sync.aligned.m16n8k16.row.col.f32.bf16.bf16.f32 "
        "{%0,%1,%2,%3}, {%4,%5,%6,%7}, {%8,%9}, {%0,%1,%2,%3};"
        : "+f"(d[0]), "+f"(d[1]), "+f"(d[2]), "+f"(d[3])
        : "r"(a[0]), "r"(a[1]), "r"(a[2]), "r"(a[3]), "r"(b0), "r"(b1));
}
#define LDMX4(r0, r1, r2, r3, addr)                                           \
    asm volatile("ldmatrix.sync.aligned.m8n8.x4.shared.b16 {%0,%1,%2,%3}, [%4];" \
        : "=r"(r0), "=r"(r1), "=r"(r2), "=r"(r3) : "r"(addr))

// ---------------- weight prep (R9 layout: 32-k tiles, [n][k]) ----------------
__global__ void prep_weights(Params P)
{
    __nv_bfloat16* ghi = (__nv_bfloat16*)g_whi4;
    __nv_bfloat16* glo = (__nv_bfloat16*)g_wlo4;
    for (int m = 0; m < 6; m++) {
        int s = m >> 1;
        bool isw2 = m & 1;
        const float* w = isw2 ? P.w2[s] : P.w1[s];
        int K   = isw2 ? 256 : (128 << s);
        int off = isw2 ? W2OFF(s) : W1OFF(s);
        int nel = K * 256;
        for (int e = blockIdx.x * blockDim.x + threadIdx.x; e < nel;
             e += gridDim.x * blockDim.x) {
            int k = e >> 8, n = e & 255;
            float v = w[e];
            __nv_bfloat16 hi = __float2bfloat16(v);
            __nv_bfloat16 lo = __float2bfloat16(v - __bfloat162float(hi));
            int d = off + (k >> 5) * 8192 + n * 32 + (k & 31);
            ghi[d] = hi;
            glo[d] = lo;
        }
    }
}

// ---------------- feat transpose: [C][HW] fp32 -> [HW][C] bf16 hi/lo ----------
__global__ void transpose_feat(const float* __restrict__ feat,
                               size_t toff, int C, int HW)
{
    __shared__ float tile[32][33];
    const int hw0 = blockIdx.x * 32;
    const int c0  = blockIdx.y * 32;
    const int b   = blockIdx.z;
    const int tx  = threadIdx.x & 31;
    const int ty  = threadIdx.x >> 5;

    const float* fb = feat + (size_t)b * C * HW;
#pragma unroll
    for (int j = 0; j < 4; j++) {
        int cc = c0 + ty + 8 * j;
        tile[ty + 8 * j][tx] = fb[(size_t)cc * HW + hw0 + tx];
    }
    __syncthreads();

    __nv_bfloat16* thi = (__nv_bfloat16*)g_thi4 + toff;
    __nv_bfloat16* tlo = (__nv_bfloat16*)g_tlo4 + toff;
    const int cp = threadIdx.x & 15;   // c-pair
    const int hb = threadIdx.x >> 4;   // 0..15
#pragma unroll
    for (int j = 0; j < 2; j++) {
        int hwl = hb + 16 * j;
        float v0 = tile[2 * cp][hwl];
        float v1 = tile[2 * cp + 1][hwl];
        uint32_t hw_, lw_;
        split2(v0, v1, hw_, lw_);
        size_t o = ((size_t)b * HW + hw0 + hwl) * C + c0 + 2 * cp;
        *(uint32_t*)(thi + o) = hw_;
        *(uint32_t*)(tlo + o) = lw_;
    }
}

// ---------------- fused kernel (R9 + coalesced A for s1/s2) ----------------
__global__ void __launch_bounds__(512, 1)
fused_mma(Params P)
{
    extern __shared__ uint32_t smw[];
    uint32_t* sxh = smw + O_SXH;
    uint32_t* sxl = smw + O_SXL;
    float*    sb1 = (float*)(smw + O_SB1);
    float*    sb2 = (float*)(smw + O_SB2);
    float*    ssp = (float*)(smw + O_SSP);
    int*      spid = (int*)(smw + O_PID);
    const uint32_t smb = s2u(smw);

    const int tid  = threadIdx.x;
    const int lane = tid & 31;
    const int wid  = tid >> 5;
    const int wm   = wid & 3;
    const int wn   = wid >> 2;
    const int gr   = lane >> 2;
    const int c    = lane & 3;
    const int rowA = wm * 16 + gr;
    const int lr   = lane & 15;
    const int lh   = lane >> 4;

    const int s  = blockIdx.x % 3;
    const int bi = blockIdx.x / 3;
    const int C  = 128 << s;
    const int HW = 32768 >> (2 * s);
    const int NT1 = C / KT;            // 4 / 8 / 16
    const int T   = NT1 + 8;

    const float* __restrict__ feat = P.feat[s];
    const int*   __restrict__ pid  = P.pid[s];

    const int row0 = bi * TM;
    const int b    = row0 >> 12;
    const int p0   = row0 & (PNUM - 1);

    if (tid < TM)  spid[tid] = pid[b * PNUM + p0 + tid];
    if (tid < 256) { sb1[tid] = __ldg(&P.b1[s][tid]); sb2[tid] = __ldg(&P.b2[s][tid]); }
    __syncthreads();

    const float* featb = feat + (size_t)b * C * HW;
    const __nv_bfloat16* ghi = (const __nv_bfloat16*)g_whi4;
    const __nv_bfloat16* glo = (const __nv_bfloat16*)g_wlo4;

    // s0 gather mapping (R9)
    const int gr0 = tid & 63;
    const int gkp = tid >> 6;          // 0..7
    const int mypid = spid[gr0];

    // s1/s2 coalesced A mapping: thread -> (row, 16B chunk), hi for tid<256
    const int arow = (tid & 255) >> 2;
    const int aq   = tid & 3;
    const __nv_bfloat16* aplane =
        (tid < 256) ? (const __nv_bfloat16*)g_thi4 : (const __nv_bfloat16*)g_tlo4;
    size_t abase = 0;
    if (s > 0)
        abase = TOFF(s) + ((size_t)b * HW + spid[arow]) * C;

    float acc[8][4];
#pragma unroll
    for (int nt = 0; nt < 8; nt++)
#pragma unroll
        for (int q = 0; q < 4; q++) acc[nt][q] = 0.f;

    uint4 pwh0, pwh1, pwl0, pwl1;      // W prefetch regs
    float va0, va1, va2, va3;          // s0 A gather prefetch
    uint4 pa;                          // s1/s2 A prefetch

    // ---- prologue: prefetch tile 0 ----
    {
        const uint4* srch = (const uint4*)(ghi + W1OFF(s));
        const uint4* srcl = (const uint4*)(glo + W1OFF(s));
        pwh0 = __ldg(&srch[tid]);  pwh1 = __ldg(&srch[tid + 512]);
        pwl0 = __ldg(&srcl[tid]);  pwl1 = __ldg(&srcl[tid + 512]);
        if (s == 0) {
            int k = gkp * 2;
            va0 = __ldg(&featb[(size_t)k * HW + mypid]);
            va1 = __ldg(&featb[(size_t)(k + 1) * HW + mypid]);
            int k2 = (gkp + 8) * 2;
            va2 = __ldg(&featb[(size_t)k2 * HW + mypid]);
            va3 = __ldg(&featb[(size_t)(k2 + 1) * HW + mypid]);
        } else {
            pa = __ldg((const uint4*)(aplane + abase) + aq);
        }
    }

    const uint32_t adrA1_h = smb + (O_SXH + (wm * 16 + lr) * 20 + lh * 4) * 4;
    const uint32_t adrA1_l = smb + (O_SXL + (wm * 16 + lr) * 20 + lh * 4) * 4;
    const uint32_t adrA2_h = smb + (O_SHH + (wm * 16 + lr) * 132 + lh * 4) * 4;
    const uint32_t adrA2_l = smb + (O_SHL + (wm * 16 + lr) * 132 + lh * 4) * 4;

    for (int t = 0; t < T; t++) {
        // ---- store prefetched W tile ----
        {
            int n0 = tid >> 2, q0 = tid & 3;
            int u1 = tid + 512;
            int n1 = u1 >> 2, q1 = u1 & 3;
            uint32_t* swh = smw + O_SWH;
            uint32_t* swl = smw + O_SWL;
            *(uint4*)((char*)swh + n0 * 80 + q0 * 16) = pwh0;
            *(uint4*)((char*)swh + n1 * 80 + q1 * 16) = pwh1;
            *(uint4*)((char*)swl + n0 * 80 + q0 * 16) = pwl0;
            *(uint4*)((char*)swl + n1 * 80 + q1 * 16) = pwl1;
        }
        // ---- store A tile ----
        if (t < NT1) {
            if (s == 0) {
                uint32_t hw, lw;
                split2(va0, va1, hw, lw);
                sxh[gr0 * 20 + gkp] = hw;
                sxl[gr0 * 20 + gkp] = lw;
                split2(va2, va3, hw, lw);
                sxh[gr0 * 20 + gkp + 8] = hw;
                sxl[gr0 * 20 + gkp + 8] = lw;
            } else {
                uint32_t* dst = (tid < 256) ? sxh : sxl;
                *(uint4*)&dst[arow * 20 + aq * 4] = pa;
            }
        }
        __syncthreads();

        // ---- prefetch tile t+1 ----
        if (t + 1 < T) {
            const int woff = (t + 1 < NT1) ? (W1OFF(s) + (t + 1) * 8192)
                                           : (W2OFF(s) + (t + 1 - NT1) * 8192);
            const uint4* srch = (const uint4*)(ghi + woff);
            const uint4* srcl = (const uint4*)(glo + woff);
            pwh0 = __ldg(&srch[tid]);  pwh1 = __ldg(&srch[tid + 512]);
            pwl0 = __ldg(&srcl[tid]);  pwl1 = __ldg(&srcl[tid + 512]);
        }
        if (t + 1 < NT1) {
            if (s == 0) {
                int k = (t + 1) * KT + gkp * 2;
                va0 = __ldg(&featb[(size_t)k * HW + mypid]);
                va1 = __ldg(&featb[(size_t)(k + 1) * HW + mypid]);
                int k2 = (t + 1) * KT + (gkp + 8) * 2;
                va2 = __ldg(&featb[(size_t)k2 * HW + mypid]);
                va3 = __ldg(&featb[(size_t)(k2 + 1) * HW + mypid]);
            } else {
                pa = __ldg((const uint4*)(aplane + abase + (t + 1) * KT) + aq);
            }
        }

        // ---- MMA phase ----
#pragma unroll
        for (int ks = 0; ks < 2; ks++) {
            uint32_t ah[4], al[4];
            if (t < NT1) {
                LDMX4(ah[0], ah[1], ah[2], ah[3], adrA1_h + ks * 32);
                LDMX4(al[0], al[1], al[2], al[3], adrA1_l + ks * 32);
            } else {
                const uint32_t koff = (uint32_t)(t - NT1) * 64 + ks * 32;
                LDMX4(ah[0], ah[1], ah[2], ah[3], adrA2_h + koff);
                LDMX4(al[0], al[1], al[2], al[3], adrA2_l + koff);
            }
            const uint32_t adrB_h = smb + (O_SWH + (wn * 64 + lr) * 20 + lh * 4) * 4;
            const uint32_t adrB_l = smb + (O_SWL + (wn * 64 + lr) * 20 + lh * 4) * 4;
#pragma unroll
            for (int p = 0; p < 4; p++) {
                uint32_t bh[4], bl[4];
                const uint32_t boff = (uint32_t)p * 16 * 80 + ks * 32;
                LDMX4(bh[0], bh[1], bh[2], bh[3], adrB_h + boff);
                LDMX4(bl[0], bl[1], bl[2], bl[3], adrB_l + boff);
                mma16816(acc[2 * p],     ah, bh[0], bh[2]);
                mma16816(acc[2 * p],     ah, bl[0], bl[2]);
                mma16816(acc[2 * p],     al, bh[0], bh[2]);
                mma16816(acc[2 * p + 1], ah, bh[1], bh[3]);
                mma16816(acc[2 * p + 1], ah, bl[1], bl[3]);
                mma16816(acc[2 * p + 1], al, bh[1], bh[3]);
            }
        }

        // ---- GEMM1->GEMM2 boundary: h epilogue ----
        if (t == NT1 - 1) {
            uint32_t* shh = smw + O_SHH;
            uint32_t* shl = smw + O_SHL;
#pragma unroll
            for (int nt = 0; nt < 8; nt++) {
                const int n  = wn * 64 + nt * 8 + 2 * c;
                const int wi = wn * 32 + nt * 4 + c;
                float v0 = fmaxf(acc[nt][0] + sb1[n],     0.f);
                float v1 = fmaxf(acc[nt][1] + sb1[n + 1], 0.f);
                float v2 = fmaxf(acc[nt][2] + sb1[n],     0.f);
                float v3 = fmaxf(acc[nt][3] + sb1[n + 1], 0.f);
                uint32_t hw, lw;
                split2(v0, v1, hw, lw);
                shh[rowA * 132 + wi] = hw;
                shl[rowA * 132 + wi] = lw;
                split2(v2, v3, hw, lw);
                shh[(rowA + 8) * 132 + wi] = hw;
                shl[(rowA + 8) * 132 + wi] = lw;
#pragma unroll
                for (int q = 0; q < 4; q++) acc[nt][q] = 0.f;
            }
        }
        __syncthreads();
    }

    // ================= epilogue: +b2, L2 normalize, store =================
    float ss0 = 0.f, ss1 = 0.f;
#pragma unroll
    for (int nt = 0; nt < 8; nt++) {
        const int n = wn * 64 + nt * 8 + 2 * c;
        acc[nt][0] += sb2[n];
        acc[nt][1] += sb2[n + 1];
        acc[nt][2] += sb2[n];
        acc[nt][3] += sb2[n + 1];
        ss0 = fmaf(acc[nt][0], acc[nt][0], fmaf(acc[nt][1], acc[nt][1], ss0));
        ss1 = fmaf(acc[nt][2], acc[nt][2], fmaf(acc[nt][3], acc[nt][3], ss1));
    }
    ss0 += __shfl_xor_sync(0xffffffffu, ss0, 1);
    ss0 += __shfl_xor_sync(0xffffffffu, ss0, 2);
    ss1 += __shfl_xor_sync(0xffffffffu, ss1, 1);
    ss1 += __shfl_xor_sync(0xffffffffu, ss1, 2);
    if (c == 0) {
        ssp[rowA * 4 + wn]       = ss0;
        ssp[(rowA + 8) * 4 + wn] = ss1;
    }
    __syncthreads();
    const float inv0 = 1.f / (sqrtf(ssp[rowA * 4] + ssp[rowA * 4 + 1] +
                                    ssp[rowA * 4 + 2] + ssp[rowA * 4 + 3]) + 1e-7f);
    const float inv1 = 1.f / (sqrtf(ssp[(rowA + 8) * 4] + ssp[(rowA + 8) * 4 + 1] +
                                    ssp[(rowA + 8) * 4 + 2] + ssp[(rowA + 8) * 4 + 3]) + 1e-7f);

    float* __restrict__ out = P.out + ((size_t)s * ROWS + row0) * NCOL;
#pragma unroll
    for (int nt = 0; nt < 8; nt++) {
        const int n = wn * 64 + nt * 8 + 2 * c;
        float2 o0 = make_float2(acc[nt][0] * inv0, acc[nt][1] * inv0);
        float2 o1 = make_float2(acc[nt][2] * inv1, acc[nt][3] * inv1);
        *(float2*)&out[(size_t)rowA * NCOL + n]       = o0;
        *(float2*)&out[(size_t)(rowA + 8) * NCOL + n] = o1;
    }
}

// ---------------- launch ----------------
extern "C" void kernel_launch(void* const* d_in, const int* in_sizes, int n_in,
                              void* d_out, int out_size)
{
    const bool sig_order = (n_in > 1) && (in_sizes[1] == 16777216);

    Params P;
    if (sig_order) {
        for (int s = 0; s < 3; s++) {
            P.feat[s] = (const float*)d_in[s];
            P.pid[s]  = (const int*)  d_in[3 + s];
            P.w1[s]   = (const float*)d_in[6 + 4 * s];
            P.b1[s]   = (const float*)d_in[7 + 4 * s];
            P.w2[s]   = (const float*)d_in[8 + 4 * s];
            P.b2[s]   = (const float*)d_in[9 + 4 * s];
        }
    } else {
        for (int s = 0; s < 3; s++) {
            P.feat[s] = (const float*)d_in[6 * s + 0];
            P.pid[s]  = (const int*)  d_in[6 * s + 1];
            P.w1[s]   = (const float*)d_in[6 * s + 2];
            P.b1[s]   = (const float*)d_in[6 * s + 3];
            P.w2[s]   = (const float*)d_in[6 * s + 4];
            P.b2[s]   = (const float*)d_in[6 * s + 5];
        }
    }
    P.out = (float*)d_out;

    cudaFuncSetAttribute(fused_mma, cudaFuncAttributeMaxDynamicSharedMemorySize,
                         SMEM_BYTES);

    prep_weights<<<256, 256>>>(P);
    // s1: C=256, HW=8192 ; s2: C=512, HW=2048
    transpose_feat<<<dim3(8192 / 32, 256 / 32, 8), 256>>>(P.feat[1], TOFF(1), 256, 8192);
    transpose_feat<<<dim3(2048 / 32, 512 / 32, 8), 256>>>(P.feat[2], TOFF(2), 512, 2048);
    fused_mma<<<3 * (ROWS / TM), 512, SMEM_BYTES>>>(P);
}

// round 12
// speedup vs baseline: 1.4093x; 1.0285x over previous
#include <cuda_runtime.h>
#include <cuda_bf16.h>
#include <math.h>
#include <stdint.h>

// ---------------- problem constants ----------------
constexpr int NCOL = 256;
constexpr int PNUM = 4096;
constexpr int ROWS = 32768;
constexpr int TM   = 64;
constexpr int KT   = 32;

__host__ __device__ constexpr int W1OFF(int s) {
    return s == 0 ? 0 : (s == 1 ? 98304 : 229376);
}
__host__ __device__ constexpr int W2OFF(int s) {
    return s == 0 ? 32768 : (s == 1 ? 163840 : 360448);
}
constexpr int WTOTAL = 425984;

__host__ __device__ constexpr size_t TOFF(int s) {
    return s == 1 ? 0 : 16777216;
}
constexpr size_t TTOTAL = 25165824;

__device__ uint4 g_whi4[WTOTAL / 8];
__device__ uint4 g_wlo4[WTOTAL / 8];
__device__ uint4 g_thi4[TTOTAL / 8];
__device__ uint4 g_tlo4[TTOTAL / 8];

// ---------------- smem word offsets ----------------
constexpr int O_SHH = 0;          // h hi: 64 x 132
constexpr int O_SHL = 8448;       // h lo
constexpr int O_SXA = 16896;      // A bufs: 2 x (hi 1280 + lo 1280)
constexpr int ABUF  = 2560;
constexpr int O_W   = 22016;      // W bufs: 2 x (hi 5120 + lo 5120)
constexpr int WBUF  = 10240;
constexpr int O_SB1 = 42496;
constexpr int O_SB2 = 42752;
constexpr int O_SSP = 43008;      // 64 rows x 8 wn
constexpr int O_PID = 43520;
constexpr int SMEM_WORDS = 43584;
constexpr int SMEM_BYTES = SMEM_WORDS * 4;   // 174,336 B

struct Params {
    const float* feat[3];
    const int*   pid[3];
    const float* w1[3];
    const float* b1[3];
    const float* w2[3];
    const float* b2[3];
    float*       out;
};

__device__ __forceinline__ uint32_t s2u(const void* p) {
    uint32_t a;
    asm("{ .reg .u64 t; cvta.to.shared.u64 t, %1; cvt.u32.u64 %0, t; }" : "=r"(a) : "l"(p));
    return a;
}
__device__ __forceinline__ uint32_t pack_bf2(__nv_bfloat16 lo, __nv_bfloat16 hi) {
    return (uint32_t)__bfloat16_as_ushort(hi) << 16 | (uint32_t)__bfloat16_as_ushort(lo);
}
__device__ __forceinline__ void split2(float v0, float v1, uint32_t& hw, uint32_t& lw) {
    __nv_bfloat16 h0 = __float2bfloat16(v0);
    __nv_bfloat16 h1 = __float2bfloat16(v1);
    __nv_bfloat16 l0 = __float2bfloat16(v0 - __bfloat162float(h0));
    __nv_bfloat16 l1 = __float2bfloat16(v1 - __bfloat162float(h1));
    hw = pack_bf2(h0, h1);
    lw = pack_bf2(l0, l1);
}
__device__ __forceinline__ void mma16816(float* d, const uint32_t* a,
                                         uint32_t b0, uint32_t b1) {
    asm volatile(
        "mma.sync.aligned.m16n8k16.row.col.f32.bf16.bf16.f32 "
        "{%0,%1,%2,%3}, {%4,%5,%6,%7}, {%8,%9}, {%0,%1,%2,%3};"
        : "+f"(d[0]), "+f"(d[1]), "+f"(d[2]), "+f"(d[3])
        : "r"(a[0]), "r"(a[1]), "r"(a[2]), "r"(a[3]), "r"(b0), "r"(b1));
}
#define LDMX4(r0, r1, r2, r3, addr)                                           \
    asm volatile("ldmatrix.sync.aligned.m8n8.x4.shared.b16 {%0,%1,%2,%3}, [%4];" \
        : "=r"(r0), "=r"(r1), "=r"(r2), "=r"(r3) : "r"(addr))

// ---------------- weight prep ----------------
__global__ void prep_weights(Params P)
{
    __nv_bfloat16* ghi = (__nv_bfloat16*)g_whi4;
    __nv_bfloat16* glo = (__nv_bfloat16*)g_wlo4;
    for (int m = 0; m < 6; m++) {
        int s = m >> 1;
        bool isw2 = m & 1;
        const float* w = isw2 ? P.w2[s] : P.w1[s];
        int K   = isw2 ? 256 : (128 << s);
        int off = isw2 ? W2OFF(s) : W1OFF(s);
        int nel = K * 256;
        for (int e = blockIdx.x * blockDim.x + threadIdx.x; e < nel;
             e += gridDim.x * blockDim.x) {
            int k = e >> 8, n = e & 255;
            float v = w[e];
            __nv_bfloat16 hi = __float2bfloat16(v);
            __nv_bfloat16 lo = __float2bfloat16(v - __bfloat162float(hi));
            int d = off + (k >> 5) * 8192 + n * 32 + (k & 31);
            ghi[d] = hi;
            glo[d] = lo;
        }
    }
}

// ---------------- feat transpose: [C][HW] fp32 -> [HW][C] bf16 hi/lo ----------
__global__ void transpose_feat(const float* __restrict__ feat,
                               size_t toff, int C, int HW)
{
    __shared__ float tile[32][33];
    const int hw0 = blockIdx.x * 32;
    const int c0  = blockIdx.y * 32;
    const int b   = blockIdx.z;
    const int tx  = threadIdx.x & 31;
    const int ty  = threadIdx.x >> 5;

    const float* fb = feat + (size_t)b * C * HW;
#pragma unroll
    for (int j = 0; j < 4; j++) {
        int cc = c0 + ty + 8 * j;
        tile[ty + 8 * j][tx] = fb[(size_t)cc * HW + hw0 + tx];
    }
    __syncthreads();

    __nv_bfloat16* thi = (__nv_bfloat16*)g_thi4 + toff;
    __nv_bfloat16* tlo = (__nv_bfloat16*)g_tlo4 + toff;
    const int cp = threadIdx.x & 15;
    const int hb = threadIdx.x >> 4;
#pragma unroll
    for (int j = 0; j < 2; j++) {
        int hwl = hb + 16 * j;
        float v0 = tile[2 * cp][hwl];
        float v1 = tile[2 * cp + 1][hwl];
        uint32_t hw_, lw_;
        split2(v0, v1, hw_, lw_);
        size_t o = ((size_t)b * HW + hw0 + hwl) * C + c0 + 2 * cp;
        *(uint32_t*)(thi + o) = hw_;
        *(uint32_t*)(tlo + o) = lw_;
    }
}

// ---------------- fused kernel: 32x32 warp tiles, dbuf smem, 1 bar/tile ------
__global__ void __launch_bounds__(512, 1)
fused_mma(Params P)
{
    extern __shared__ uint32_t smw[];
    float*    sb1 = (float*)(smw + O_SB1);
    float*    sb2 = (float*)(smw + O_SB2);
    float*    ssp = (float*)(smw + O_SSP);
    int*      spid = (int*)(smw + O_PID);
    const uint32_t smb = s2u(smw);

    const int tid  = threadIdx.x;
    const int lane = tid & 31;
    const int wid  = tid >> 5;
    const int wm   = wid & 1;          // rows wm*32..+31
    const int wn   = wid >> 1;         // cols wn*32..+31
    const int gr   = lane >> 2;
    const int c    = lane & 3;
    const int lr   = lane & 15;
    const int lh   = lane >> 4;

    const int s  = blockIdx.x % 3;
    const int bi = blockIdx.x / 3;
    const int C  = 128 << s;
    const int HW = 32768 >> (2 * s);
    const int NT1 = C / KT;            // 4 / 8 / 16
    const int T   = NT1 + 8;

    const float* __restrict__ feat = P.feat[s];
    const int*   __restrict__ pid  = P.pid[s];

    const int row0 = bi * TM;
    const int b    = row0 >> 12;
    const int p0   = row0 & (PNUM - 1);

    if (tid < TM)  spid[tid] = pid[b * PNUM + p0 + tid];
    if (tid < 256) { sb1[tid] = __ldg(&P.b1[s][tid]); sb2[tid] = __ldg(&P.b2[s][tid]); }
    __syncthreads();

    const float* featb = feat + (size_t)b * C * HW;
    const __nv_bfloat16* ghi = (const __nv_bfloat16*)g_whi4;
    const __nv_bfloat16* glo = (const __nv_bfloat16*)g_wlo4;

    // s0 gather mapping
    const int gr0 = tid & 63;
    const int gkp = tid >> 6;
    const int mypid = spid[gr0];

    // s1/s2 coalesced A mapping
    const int arow = (tid & 255) >> 2;
    const int aq   = tid & 3;
    const __nv_bfloat16* aplane =
        (tid < 256) ? (const __nv_bfloat16*)g_thi4 : (const __nv_bfloat16*)g_tlo4;
    size_t abase = 0;
    if (s > 0)
        abase = TOFF(s) + ((size_t)b * HW + spid[arow]) * C;

    float acc[2][4][4];
#pragma unroll
    for (int mt = 0; mt < 2; mt++)
#pragma unroll
        for (int nt = 0; nt < 4; nt++)
#pragma unroll
            for (int q = 0; q < 4; q++) acc[mt][nt][q] = 0.f;

    uint4 pwh0, pwh1, pwl0, pwl1;
    float va0, va1, va2, va3;
    uint4 pa;

    auto loadW = [&](int t) {
        const int woff = (t < NT1) ? (W1OFF(s) + t * 8192)
                                   : (W2OFF(s) + (t - NT1) * 8192);
        const uint4* srch = (const uint4*)(ghi + woff);
        const uint4* srcl = (const uint4*)(glo + woff);
        pwh0 = __ldg(&srch[tid]);  pwh1 = __ldg(&srch[tid + 512]);
        pwl0 = __ldg(&srcl[tid]);  pwl1 = __ldg(&srcl[tid + 512]);
    };
    auto storeW = [&](int t) {
        uint32_t* swh = smw + O_W + (t & 1) * WBUF;
        uint32_t* swl = swh + 5120;
        int n0 = tid >> 2, q0 = tid & 3;
        int u1 = tid + 512, n1 = u1 >> 2, q1 = u1 & 3;
        *(uint4*)((char*)swh + n0 * 80 + q0 * 16) = pwh0;
        *(uint4*)((char*)swh + n1 * 80 + q1 * 16) = pwh1;
        *(uint4*)((char*)swl + n0 * 80 + q0 * 16) = pwl0;
        *(uint4*)((char*)swl + n1 * 80 + q1 * 16) = pwl1;
    };
    auto loadA = [&](int t) {
        if (s == 0) {
            int k = t * KT + gkp * 2;
            va0 = __ldg(&featb[(size_t)k * HW + mypid]);
            va1 = __ldg(&featb[(size_t)(k + 1) * HW + mypid]);
            int k2 = t * KT + (gkp + 8) * 2;
            va2 = __ldg(&featb[(size_t)k2 * HW + mypid]);
            va3 = __ldg(&featb[(size_t)(k2 + 1) * HW + mypid]);
        } else {
            pa = __ldg((const uint4*)(aplane + abase + t * KT) + aq);
        }
    };
    auto storeA = [&](int t) {
        uint32_t* axh = smw + O_SXA + (t & 1) * ABUF;
        uint32_t* axl = axh + 1280;
        if (s == 0) {
            uint32_t hw, lw;
            split2(va0, va1, hw, lw);
            axh[gr0 * 20 + gkp] = hw;
            axl[gr0 * 20 + gkp] = lw;
            split2(va2, va3, hw, lw);
            axh[gr0 * 20 + gkp + 8] = hw;
            axl[gr0 * 20 + gkp + 8] = lw;
        } else {
            uint32_t* dst = (tid < 256) ? axh : axl;
            *(uint4*)&dst[arow * 20 + aq * 4] = pa;
        }
    };

    // ---- prologue: tile 0 into buf0 ----
    loadW(0);
    loadA(0);
    storeW(0);
    storeA(0);
    __syncthreads();

    for (int t = 0; t < T; t++) {
        // ---- GEMM1->GEMM2 boundary: write h, then sync before GEMM2 reads ----
        if (t == NT1) {
            uint32_t* shh = smw + O_SHH;
            uint32_t* shl = smw + O_SHL;
#pragma unroll
            for (int mt = 0; mt < 2; mt++) {
                const int rH = wm * 32 + mt * 16 + gr;
#pragma unroll
                for (int nt = 0; nt < 4; nt++) {
                    const int n  = wn * 32 + nt * 8 + 2 * c;
                    const int wi = wn * 16 + nt * 4 + c;
                    float v0 = fmaxf(acc[mt][nt][0] + sb1[n],     0.f);
                    float v1 = fmaxf(acc[mt][nt][1] + sb1[n + 1], 0.f);
                    float v2 = fmaxf(acc[mt][nt][2] + sb1[n],     0.f);
                    float v3 = fmaxf(acc[mt][nt][3] + sb1[n + 1], 0.f);
                    uint32_t hw, lw;
                    split2(v0, v1, hw, lw);
                    shh[rH * 132 + wi] = hw;
                    shl[rH * 132 + wi] = lw;
                    split2(v2, v3, hw, lw);
                    shh[(rH + 8) * 132 + wi] = hw;
                    shl[(rH + 8) * 132 + wi] = lw;
#pragma unroll
                    for (int q = 0; q < 4; q++) acc[mt][nt][q] = 0.f;
                }
            }
            __syncthreads();
        }

        // ---- prefetch t+1 into registers (lands during MMA) ----
        if (t + 1 < T)   loadW(t + 1);
        if (t + 1 < NT1) loadA(t + 1);

        // ---- MMA phase on buffers (t&1) ----
        const uint32_t bsel = (uint32_t)(t & 1);
#pragma unroll
        for (int ks = 0; ks < 2; ks++) {
            uint32_t ah0[4], ah1[4], al0[4], al1[4];
            if (t < NT1) {
                const uint32_t base = smb +
                    (O_SXA + bsel * ABUF + (wm * 32 + lr) * 20 + ks * 8 + lh * 4) * 4;
                LDMX4(ah0[0], ah0[1], ah0[2], ah0[3], base);
                LDMX4(ah1[0], ah1[1], ah1[2], ah1[3], base + 16 * 20 * 4);
                LDMX4(al0[0], al0[1], al0[2], al0[3], base + 1280 * 4);
                LDMX4(al1[0], al1[1], al1[2], al1[3], base + (1280 + 16 * 20) * 4);
            } else {
                const uint32_t base = smb +
                    (O_SHH + (wm * 32 + lr) * 132 + (t - NT1) * 16 + ks * 8 + lh * 4) * 4;
                LDMX4(ah0[0], ah0[1], ah0[2], ah0[3], base);
                LDMX4(ah1[0], ah1[1], ah1[2], ah1[3], base + 16 * 132 * 4);
                LDMX4(al0[0], al0[1], al0[2], al0[3], base + 8448 * 4);
                LDMX4(al1[0], al1[1], al1[2], al1[3], base + (8448 + 16 * 132) * 4);
            }
#pragma unroll
            for (int p = 0; p < 2; p++) {
                uint32_t bh[4], bl[4];
                const uint32_t bbase = smb +
                    (O_W + bsel * WBUF + (wn * 32 + p * 16 + lr) * 20 + ks * 8 + lh * 4) * 4;
                LDMX4(bh[0], bh[1], bh[2], bh[3], bbase);
                LDMX4(bl[0], bl[1], bl[2], bl[3], bbase + 5120 * 4);
                mma16816(acc[0][2 * p],     ah0, bh[0], bh[2]);
                mma16816(acc[0][2 * p],     ah0, bl[0], bl[2]);
                mma16816(acc[0][2 * p],     al0, bh[0], bh[2]);
                mma16816(acc[0][2 * p + 1], ah0, bh[1], bh[3]);
                mma16816(acc[0][2 * p + 1], ah0, bl[1], bl[3]);
                mma16816(acc[0][2 * p + 1], al0, bh[1], bh[3]);
                mma16816(acc[1][2 * p],     ah1, bh[0], bh[2]);
                mma16816(acc[1][2 * p],     ah1, bl[0], bl[2]);
                mma16816(acc[1][2 * p],     al1, bh[0], bh[2]);
                mma16816(acc[1][2 * p + 1], ah1, bh[1], bh[3]);
                mma16816(acc[1][2 * p + 1], ah1, bl[1], bl[3]);
                mma16816(acc[1][2 * p + 1], al1, bh[1], bh[3]);
            }
        }

        // ---- store prefetched regs into the idle buffers ----
        if (t + 1 < T)   storeW(t + 1);
        if (t + 1 < NT1) storeA(t + 1);
        __syncthreads();
    }

    // ================= epilogue: +b2, L2 normalize, store =================
#pragma unroll
    for (int mt = 0; mt < 2; mt++) {
        float ss0 = 0.f, ss1 = 0.f;
#pragma unroll
        for (int nt = 0; nt < 4; nt++) {
            const int n = wn * 32 + nt * 8 + 2 * c;
            acc[mt][nt][0] += sb2[n];
            acc[mt][nt][1] += sb2[n + 1];
            acc[mt][nt][2] += sb2[n];
            acc[mt][nt][3] += sb2[n + 1];
            ss0 = fmaf(acc[mt][nt][0], acc[mt][nt][0],
                  fmaf(acc[mt][nt][1], acc[mt][nt][1], ss0));
            ss1 = fmaf(acc[mt][nt][2], acc[mt][nt][2],
                  fmaf(acc[mt][nt][3], acc[mt][nt][3], ss1));
        }
        ss0 += __shfl_xor_sync(0xffffffffu, ss0, 1);
        ss0 += __shfl_xor_sync(0xffffffffu, ss0, 2);
        ss1 += __shfl_xor_sync(0xffffffffu, ss1, 1);
        ss1 += __shfl_xor_sync(0xffffffffu, ss1, 2);
        if (c == 0) {
            const int rE = wm * 32 + mt * 16 + gr;
            ssp[rE * 8 + wn]       = ss0;
            ssp[(rE + 8) * 8 + wn] = ss1;
        }
    }
    __syncthreads();

    float* __restrict__ out = P.out + ((size_t)s * ROWS + row0) * NCOL;
#pragma unroll
    for (int mt = 0; mt < 2; mt++) {
        const int rE = wm * 32 + mt * 16 + gr;
        float s0a = 0.f, s1a = 0.f;
#pragma unroll
        for (int j = 0; j < 8; j++) {
            s0a += ssp[rE * 8 + j];
            s1a += ssp[(rE + 8) * 8 + j];
        }
        const float inv0 = 1.f / (sqrtf(s0a) + 1e-7f);
        const float inv1 = 1.f / (sqrtf(s1a) + 1e-7f);
#pragma unroll
        for (int nt = 0; nt < 4; nt++) {
            const int n = wn * 32 + nt * 8 + 2 * c;
            float2 o0 = make_float2(acc[mt][nt][0] * inv0, acc[mt][nt][1] * inv0);
            float2 o1 = make_float2(acc[mt][nt][2] * inv1, acc[mt][nt][3] * inv1);
            *(float2*)&out[(size_t)rE * NCOL + n]       = o0;
            *(float2*)&out[(size_t)(rE + 8) * NCOL + n] = o1;
        }
    }
}

// ---------------- launch ----------------
extern "C" void kernel_launch(void* const* d_in, const int* in_sizes, int n_in,
                              void* d_out, int out_size)
{
    const bool sig_order = (n_in > 1) && (in_sizes[1] == 16777216);

    Params P;
    if (sig_order) {
        for (int s = 0; s < 3; s++) {
            P.feat[s] = (const float*)d_in[s];
            P.pid[s]  = (const int*)  d_in[3 + s];
            P.w1[s]   = (const float*)d_in[6 + 4 * s];
            P.b1[s]   = (const float*)d_in[7 + 4 * s];
            P.w2[s]   = (const float*)d_in[8 + 4 * s];
            P.b2[s]   = (const float*)d_in[9 + 4 * s];
        }
    } else {
        for (int s = 0; s < 3; s++) {
            P.feat[s] = (const float*)d_in[6 * s + 0];
            P.pid[s]  = (const int*)  d_in[6 * s + 1];
            P.w1[s]   = (const float*)d_in[6 * s + 2];
            P.b1[s]   = (const float*)d_in[6 * s + 3];
            P.w2[s]   = (const float*)d_in[6 * s + 4];
            P.b2[s]   = (const float*)d_in[6 * s + 5];
        }
    }
    P.out = (float*)d_out;

    cudaFuncSetAttribute(fused_mma, cudaFuncAttributeMaxDynamicSharedMemorySize,
                         SMEM_BYTES);

    prep_weights<<<256, 256>>>(P);
    transpose_feat<<<dim3(8192 / 32, 256 / 32, 8), 256>>>(P.feat[1], TOFF(1), 256, 8192);
    transpose_feat<<<dim3(2048 / 32, 512 / 32, 8), 256>>>(P.feat[2], TOFF(2), 512, 2048);
    fused_mma<<<3 * (ROWS / TM), 512, SMEM_BYTES>>>(P);
}

// round 13
// speedup vs baseline: 1.5370x; 1.0906x over previous
#include <cuda_runtime.h>
#include <cuda_bf16.h>
#include <math.h>
#include <stdint.h>

// ---------------- problem constants ----------------
constexpr int NCOL = 256;
constexpr int PNUM = 4096;
constexpr int ROWS = 32768;
constexpr int TM   = 64;
constexpr int KT   = 32;

__host__ __device__ constexpr int W1OFF(int s) {
    return s == 0 ? 0 : (s == 1 ? 98304 : 229376);
}
__host__ __device__ constexpr int W2OFF(int s) {
    return s == 0 ? 32768 : (s == 1 ? 163840 : 360448);
}
constexpr int WTOTAL = 425984;

__host__ __device__ constexpr size_t TOFF(int s) {
    return s == 1 ? 0 : 16777216;
}
constexpr size_t TTOTAL = 25165824;

__device__ uint4 g_whi4[WTOTAL / 8];   // W bf16 hi, FRAGMENT layout
__device__ uint4 g_wlo4[WTOTAL / 8];   // lo residuals, FRAGMENT layout
__device__ uint4 g_thi4[TTOTAL / 8];   // feat^T bf16 hi (s1, s2)
__device__ uint4 g_tlo4[TTOTAL / 8];

// ---------------- smem word offsets ----------------
constexpr int O_SHH = 0;          // h hi: 64 x 132
constexpr int O_SHL = 8448;       // h lo
constexpr int O_SXA = 16896;      // A bufs: 2 x (hi 1280 + lo 1280)
constexpr int ABUF  = 2560;
constexpr int O_SB1 = 22016;
constexpr int O_SB2 = 22272;
constexpr int O_SSP = 22528;      // 64 rows x 8 wn
constexpr int O_PID = 23040;
constexpr int SMEM_WORDS = 23104;
constexpr int SMEM_BYTES = SMEM_WORDS * 4;   // 92,416 B

struct Params {
    const float* feat[3];
    const int*   pid[3];
    const float* w1[3];
    const float* b1[3];
    const float* w2[3];
    const float* b2[3];
    float*       out;
};

__device__ __forceinline__ uint32_t s2u(const void* p) {
    uint32_t a;
    asm("{ .reg .u64 t; cvta.to.shared.u64 t, %1; cvt.u32.u64 %0, t; }" : "=r"(a) : "l"(p));
    return a;
}
__device__ __forceinline__ uint32_t pack_bf2(__nv_bfloat16 lo, __nv_bfloat16 hi) {
    return (uint32_t)__bfloat16_as_ushort(hi) << 16 | (uint32_t)__bfloat16_as_ushort(lo);
}
__device__ __forceinline__ void split2(float v0, float v1, uint32_t& hw, uint32_t& lw) {
    __nv_bfloat16 h0 = __float2bfloat16(v0);
    __nv_bfloat16 h1 = __float2bfloat16(v1);
    __nv_bfloat16 l0 = __float2bfloat16(v0 - __bfloat162float(h0));
    __nv_bfloat16 l1 = __float2bfloat16(v1 - __bfloat162float(h1));
    hw = pack_bf2(h0, h1);
    lw = pack_bf2(l0, l1);
}
__device__ __forceinline__ void mma16816(float* d, const uint32_t* a,
                                         uint32_t b0, uint32_t b1) {
    asm volatile(
        "mma.sync.aligned.m16n8k16.row.col.f32.bf16.bf16.f32 "
        "{%0,%1,%2,%3}, {%4,%5,%6,%7}, {%8,%9}, {%0,%1,%2,%3};"
        : "+f"(d[0]), "+f"(d[1]), "+f"(d[2]), "+f"(d[3])
        : "r"(a[0]), "r"(a[1]), "r"(a[2]), "r"(a[3]), "r"(b0), "r"(b1));
}
#define LDMX4(r0, r1, r2, r3, addr)                                           \
    asm volatile("ldmatrix.sync.aligned.m8n8.x4.shared.b16 {%0,%1,%2,%3}, [%4];" \
        : "=r"(r0), "=r"(r1), "=r"(r2), "=r"(r3) : "r"(addr))

// ---------------- weight prep: fragment-ordered bf16 hi/lo ----------------
// Unit layout per 32-k tile (8192 bf16): [ks(2)][np(16)][lane(32)][word(4)]
//   word w at lane l of (ks, np): wsel = ((kk>>3)<<1) | (nt&1)
//   lane = (n&7)*4 + ((kk&7)>>1), np = nt>>1, nt = n>>3, kk = k&15
__global__ void prep_weights(Params P)
{
    __nv_bfloat16* ghi = (__nv_bfloat16*)g_whi4;
    __nv_bfloat16* glo = (__nv_bfloat16*)g_wlo4;
    for (int m = 0; m < 6; m++) {
        int s = m >> 1;
        bool isw2 = m & 1;
        const float* w = isw2 ? P.w2[s] : P.w1[s];
        int K   = isw2 ? 256 : (128 << s);
        int off = isw2 ? W2OFF(s) : W1OFF(s);
        int nel = K * 256;
        for (int e = blockIdx.x * blockDim.x + threadIdx.x; e < nel;
             e += gridDim.x * blockDim.x) {
            int k = e >> 8, n = e & 255;
            float v = w[e];
            __nv_bfloat16 hi = __float2bfloat16(v);
            __nv_bfloat16 lo = __float2bfloat16(v - __bfloat162float(hi));
            int tile = k >> 5, ks = (k >> 4) & 1, kk = k & 15;
            int nt   = n >> 3, np = nt >> 1;
            int lane = (n & 7) * 4 + ((kk & 7) >> 1);
            int wsel = ((kk >> 3) << 1) | (nt & 1);
            int widx = (((tile * 2 + ks) * 16 + np) * 32 + lane) * 4 + wsel;
            int d    = off + widx * 2 + (k & 1);
            ghi[d] = hi;
            glo[d] = lo;
        }
    }
}

// ---------------- feat transpose: [C][HW] fp32 -> [HW][C] bf16 hi/lo ----------
__global__ void transpose_feat(const float* __restrict__ feat,
                               size_t toff, int C, int HW)
{
    __shared__ float tile[32][33];
    const int hw0 = blockIdx.x * 32;
    const int c0  = blockIdx.y * 32;
    const int b   = blockIdx.z;
    const int tx  = threadIdx.x & 31;
    const int ty  = threadIdx.x >> 5;

    const float* fb = feat + (size_t)b * C * HW;
#pragma unroll
    for (int j = 0; j < 4; j++) {
        int cc = c0 + ty + 8 * j;
        tile[ty + 8 * j][tx] = fb[(size_t)cc * HW + hw0 + tx];
    }
    __syncthreads();

    __nv_bfloat16* thi = (__nv_bfloat16*)g_thi4 + toff;
    __nv_bfloat16* tlo = (__nv_bfloat16*)g_tlo4 + toff;
    const int cp = threadIdx.x & 15;
    const int hb = threadIdx.x >> 4;
#pragma unroll
    for (int j = 0; j < 2; j++) {
        int hwl = hb + 16 * j;
        float v0 = tile[2 * cp][hwl];
        float v1 = tile[2 * cp + 1][hwl];
        uint32_t hw_, lw_;
        split2(v0, v1, hw_, lw_);
        size_t o = ((size_t)b * HW + hw0 + hwl) * C + c0 + 2 * cp;
        *(uint32_t*)(thi + o) = hw_;
        *(uint32_t*)(tlo + o) = lw_;
    }
}

// ---------------- fused kernel: B fragments direct from gmem ----------------
__global__ void __launch_bounds__(512, 1)
fused_mma(Params P)
{
    extern __shared__ uint32_t smw[];
    float*    sb1 = (float*)(smw + O_SB1);
    float*    sb2 = (float*)(smw + O_SB2);
    float*    ssp = (float*)(smw + O_SSP);
    int*      spid = (int*)(smw + O_PID);
    const uint32_t smb = s2u(smw);

    const int tid  = threadIdx.x;
    const int lane = tid & 31;
    const int wid  = tid >> 5;
    const int wm   = wid & 1;          // rows wm*32..+31
    const int wn   = wid >> 1;         // cols wn*32..+31
    const int gr   = lane >> 2;
    const int c    = lane & 3;
    const int lr   = lane & 15;
    const int lh   = lane >> 4;

    const int s  = blockIdx.x % 3;
    const int bi = blockIdx.x / 3;
    const int C  = 128 << s;
    const int HW = 32768 >> (2 * s);
    const int NT1 = C / KT;            // 4 / 8 / 16
    const int T   = NT1 + 8;

    const float* __restrict__ feat = P.feat[s];
    const int*   __restrict__ pid  = P.pid[s];

    const int row0 = bi * TM;
    const int b    = row0 >> 12;
    const int p0   = row0 & (PNUM - 1);

    if (tid < TM)  spid[tid] = pid[b * PNUM + p0 + tid];
    if (tid < 256) { sb1[tid] = __ldg(&P.b1[s][tid]); sb2[tid] = __ldg(&P.b2[s][tid]); }
    __syncthreads();

    const float* featb = feat + (size_t)b * C * HW;
    const __nv_bfloat16* ghi = (const __nv_bfloat16*)g_whi4;
    const __nv_bfloat16* glo = (const __nv_bfloat16*)g_wlo4;

    // s0 gather mapping
    const int gr0 = tid & 63;
    const int gkp = tid >> 6;
    const int mypid = spid[gr0];

    // s1/s2 coalesced A mapping
    const int arow = (tid & 255) >> 2;
    const int aq   = tid & 3;
    const __nv_bfloat16* aplane =
        (tid < 256) ? (const __nv_bfloat16*)g_thi4 : (const __nv_bfloat16*)g_tlo4;
    size_t abase = 0;
    if (s > 0)
        abase = TOFF(s) + ((size_t)b * HW + spid[arow]) * C;

    float acc[2][4][4];
#pragma unroll
    for (int mt = 0; mt < 2; mt++)
#pragma unroll
        for (int nt = 0; nt < 4; nt++)
#pragma unroll
            for (int q = 0; q < 4; q++) acc[mt][nt][q] = 0.f;

    float va0, va1, va2, va3;
    uint4 pa;

    auto loadA = [&](int t) {
        if (s == 0) {
            int k = t * KT + gkp * 2;
            va0 = __ldg(&featb[(size_t)k * HW + mypid]);
            va1 = __ldg(&featb[(size_t)(k + 1) * HW + mypid]);
            int k2 = t * KT + (gkp + 8) * 2;
            va2 = __ldg(&featb[(size_t)k2 * HW + mypid]);
            va3 = __ldg(&featb[(size_t)(k2 + 1) * HW + mypid]);
        } else {
            pa = __ldg((const uint4*)(aplane + abase + t * KT) + aq);
        }
    };
    auto storeA = [&](int t) {
        uint32_t* axh = smw + O_SXA + (t & 1) * ABUF;
        uint32_t* axl = axh + 1280;
        if (s == 0) {
            uint32_t hw, lw;
            split2(va0, va1, hw, lw);
            axh[gr0 * 20 + gkp] = hw;
            axl[gr0 * 20 + gkp] = lw;
            split2(va2, va3, hw, lw);
            axh[gr0 * 20 + gkp + 8] = hw;
            axl[gr0 * 20 + gkp + 8] = lw;
        } else {
            uint32_t* dst = (tid < 256) ? axh : axl;
            *(uint4*)&dst[arow * 20 + aq * 4] = pa;
        }
    };

    // ---- prologue: A tile 0 into buf0 ----
    loadA(0);
    storeA(0);
    __syncthreads();

    for (int t = 0; t < T; t++) {
        // ---- GEMM1->GEMM2 boundary: write h, sync before GEMM2 LDSM reads ----
        if (t == NT1) {
            uint32_t* shh = smw + O_SHH;
            uint32_t* shl = smw + O_SHL;
#pragma unroll
            for (int mt = 0; mt < 2; mt++) {
                const int rH = wm * 32 + mt * 16 + gr;
#pragma unroll
                for (int nt = 0; nt < 4; nt++) {
                    const int n  = wn * 32 + nt * 8 + 2 * c;
                    const int wi = wn * 16 + nt * 4 + c;
                    float v0 = fmaxf(acc[mt][nt][0] + sb1[n],     0.f);
                    float v1 = fmaxf(acc[mt][nt][1] + sb1[n + 1], 0.f);
                    float v2 = fmaxf(acc[mt][nt][2] + sb1[n],     0.f);
                    float v3 = fmaxf(acc[mt][nt][3] + sb1[n + 1], 0.f);
                    uint32_t hw, lw;
                    split2(v0, v1, hw, lw);
                    shh[rH * 132 + wi] = hw;
                    shl[rH * 132 + wi] = lw;
                    split2(v2, v3, hw, lw);
                    shh[(rH + 8) * 132 + wi] = hw;
                    shl[(rH + 8) * 132 + wi] = lw;
#pragma unroll
                    for (int q = 0; q < 4; q++) acc[mt][nt][q] = 0.f;
                }
            }
            __syncthreads();
        }

        // ---- prefetch A(t+1) into registers ----
        if (t + 1 < NT1) loadA(t + 1);

        // ---- B fragment base for this tile (gmem, L2-hot) ----
        const int woff = (t < NT1) ? (W1OFF(s) + t * 8192)
                                   : (W2OFF(s) + (t - NT1) * 8192);
        const uint4* fbh = (const uint4*)(ghi + woff);
        const uint4* fbl = (const uint4*)(glo + woff);

        // ---- MMA phase ----
        const uint32_t bsel = (uint32_t)(t & 1);
#pragma unroll
        for (int ks = 0; ks < 2; ks++) {
            uint32_t ah0[4], ah1[4], al0[4], al1[4];
            if (t < NT1) {
                const uint32_t base = smb +
                    (O_SXA + bsel * ABUF + (wm * 32 + lr) * 20 + ks * 8 + lh * 4) * 4;
                LDMX4(ah0[0], ah0[1], ah0[2], ah0[3], base);
                LDMX4(ah1[0], ah1[1], ah1[2], ah1[3], base + 16 * 20 * 4);
                LDMX4(al0[0], al0[1], al0[2], al0[3], base + 1280 * 4);
                LDMX4(al1[0], al1[1], al1[2], al1[3], base + (1280 + 16 * 20) * 4);
            } else {
                const uint32_t base = smb +
                    (O_SHH + (wm * 32 + lr) * 132 + (t - NT1) * 16 + ks * 8 + lh * 4) * 4;
                LDMX4(ah0[0], ah0[1], ah0[2], ah0[3], base);
                LDMX4(ah1[0], ah1[1], ah1[2], ah1[3], base + 16 * 132 * 4);
                LDMX4(al0[0], al0[1], al0[2], al0[3], base + 8448 * 4);
                LDMX4(al1[0], al1[1], al1[2], al1[3], base + (8448 + 16 * 132) * 4);
            }
#pragma unroll
            for (int p = 0; p < 2; p++) {
                const int u = ((ks * 16) + wn * 2 + p) * 32 + lane;
                uint4 bh = __ldg(&fbh[u]);
                uint4 bl = __ldg(&fbl[u]);
                mma16816(acc[0][2 * p],     ah0, bh.x, bh.z);
                mma16816(acc[0][2 * p],     ah0, bl.x, bl.z);
                mma16816(acc[0][2 * p],     al0, bh.x, bh.z);
                mma16816(acc[0][2 * p + 1], ah0, bh.y, bh.w);
                mma16816(acc[0][2 * p + 1], ah0, bl.y, bl.w);
                mma16816(acc[0][2 * p + 1], al0, bh.y, bh.w);
                mma16816(acc[1][2 * p],     ah1, bh.x, bh.z);
                mma16816(acc[1][2 * p],     ah1, bl.x, bl.z);
                mma16816(acc[1][2 * p],     al1, bh.x, bh.z);
                mma16816(acc[1][2 * p + 1], ah1, bh.y, bh.w);
                mma16816(acc[1][2 * p + 1], ah1, bl.y, bl.w);
                mma16816(acc[1][2 * p + 1], al1, bh.y, bh.w);
            }
        }

        // ---- store prefetched A into the idle buffer; sync only in GEMM1 ----
        if (t + 1 < NT1) storeA(t + 1);
        if (t < NT1) __syncthreads();
    }

    // ================= epilogue: +b2, L2 normalize, store =================
#pragma unroll
    for (int mt = 0; mt < 2; mt++) {
        float ss0 = 0.f, ss1 = 0.f;
#pragma unroll
        for (int nt = 0; nt < 4; nt++) {
            const int n = wn * 32 + nt * 8 + 2 * c;
            acc[mt][nt][0] += sb2[n];
            acc[mt][nt][1] += sb2[n + 1];
            acc[mt][nt][2] += sb2[n];
            acc[mt][nt][3] += sb2[n + 1];
            ss0 = fmaf(acc[mt][nt][0], acc[mt][nt][0],
                  fmaf(acc[mt][nt][1], acc[mt][nt][1], ss0));
            ss1 = fmaf(acc[mt][nt][2], acc[mt][nt][2],
                  fmaf(acc[mt][nt][3], acc[mt][nt][3], ss1));
        }
        ss0 += __shfl_xor_sync(0xffffffffu, ss0, 1);
        ss0 += __shfl_xor_sync(0xffffffffu, ss0, 2);
        ss1 += __shfl_xor_sync(0xffffffffu, ss1, 1);
        ss1 += __shfl_xor_sync(0xffffffffu, ss1, 2);
        if (c == 0) {
            const int rE = wm * 32 + mt * 16 + gr;
            ssp[rE * 8 + wn]       = ss0;
            ssp[(rE + 8) * 8 + wn] = ss1;
        }
    }
    __syncthreads();

    float* __restrict__ out = P.out + ((size_t)s * ROWS + row0) * NCOL;
#pragma unroll
    for (int mt = 0; mt < 2; mt++) {
        const int rE = wm * 32 + mt * 16 + gr;
        float s0a = 0.f, s1a = 0.f;
#pragma unroll
        for (int j = 0; j < 8; j++) {
            s0a += ssp[rE * 8 + j];
            s1a += ssp[(rE + 8) * 8 + j];
        }
        const float inv0 = 1.f / (sqrtf(s0a) + 1e-7f);
        const float inv1 = 1.f / (sqrtf(s1a) + 1e-7f);
#pragma unroll
        for (int nt = 0; nt < 4; nt++) {
            const int n = wn * 32 + nt * 8 + 2 * c;
            float2 o0 = make_float2(acc[mt][nt][0] * inv0, acc[mt][nt][1] * inv0);
            float2 o1 = make_float2(acc[mt][nt][2] * inv1, acc[mt][nt][3] * inv1);
            *(float2*)&out[(size_t)rE * NCOL + n]       = o0;
            *(float2*)&out[(size_t)(rE + 8) * NCOL + n] = o1;
        }
    }
}

// ---------------- launch ----------------
extern "C" void kernel_launch(void* const* d_in, const int* in_sizes, int n_in,
                              void* d_out, int out_size)
{
    const bool sig_order = (n_in > 1) && (in_sizes[1] == 16777216);

    Params P;
    if (sig_order) {
        for (int s = 0; s < 3; s++) {
            P.feat[s] = (const float*)d_in[s];
            P.pid[s]  = (const int*)  d_in[3 + s];
            P.w1[s]   = (const float*)d_in[6 + 4 * s];
            P.b1[s]   = (const float*)d_in[7 + 4 * s];
            P.w2[s]   = (const float*)d_in[8 + 4 * s];
            P.b2[s]   = (const float*)d_in[9 + 4 * s];
        }
    } else {
        for (int s = 0; s < 3; s++) {
            P.feat[s] = (const float*)d_in[6 * s + 0];
            P.pid[s]  = (const int*)  d_in[6 * s + 1];
            P.w1[s]   = (const float*)d_in[6 * s + 2];
            P.b1[s]   = (const float*)d_in[6 * s + 3];
            P.w2[s]   = (const float*)d_in[6 * s + 4];
            P.b2[s]   = (const float*)d_in[6 * s + 5];
        }
    }
    P.out = (float*)d_out;

    cudaFuncSetAttribute(fused_mma, cudaFuncAttributeMaxDynamicSharedMemorySize,
                         SMEM_BYTES);

    prep_weights<<<256, 256>>>(P);
    transpose_feat<<<dim3(8192 / 32, 256 / 32, 8), 256>>>(P.feat[1], TOFF(1), 256, 8192);
    transpose_feat<<<dim3(2048 / 32, 512 / 32, 8), 256>>>(P.feat[2], TOFF(2), 512, 2048);
    fused_mma<<<3 * (ROWS / TM), 512, SMEM_BYTES>>>(P);
}

// round 14
// speedup vs baseline: 2.5805x; 1.6789x over previous
#include <cuda_runtime.h>
#include <cuda_fp16.h>
#include <math.h>
#include <stdint.h>

// ---------------- problem constants ----------------
constexpr int NCOL = 256;
constexpr int PNUM = 4096;
constexpr int ROWS = 32768;
constexpr int TM   = 64;
constexpr int KT   = 32;

__host__ __device__ constexpr int W1OFF(int s) {
    return s == 0 ? 0 : (s == 1 ? 98304 : 229376);
}
__host__ __device__ constexpr int W2OFF(int s) {
    return s == 0 ? 32768 : (s == 1 ? 163840 : 360448);
}
constexpr int WTOTAL = 425984;

__host__ __device__ constexpr size_t TOFF(int s) {
    return s == 1 ? 0 : 16777216;
}
constexpr size_t TTOTAL = 25165824;

__device__ uint4 g_w4[WTOTAL / 8];    // W fp16, FRAGMENT layout
__device__ uint4 g_t4[TTOTAL / 8];    // feat^T fp16 (s1, s2)

// ---------------- smem word offsets ----------------
constexpr int O_SHH = 0;          // h: 64 x 132 words (fp16x2)
constexpr int O_SXA = 8448;       // A bufs: 2 x 1280 (64 rows x 20 words)
constexpr int ABUF  = 1280;
constexpr int O_SB1 = 11008;
constexpr int O_SB2 = 11264;
constexpr int O_SSP = 11520;      // 64 rows x 8 wn
constexpr int O_PID = 12032;
constexpr int SMEM_WORDS = 12096;
constexpr int SMEM_BYTES = SMEM_WORDS * 4;   // 48,384 B

struct Params {
    const float* feat[3];
    const int*   pid[3];
    const float* w1[3];
    const float* b1[3];
    const float* w2[3];
    const float* b2[3];
    float*       out;
};

__device__ __forceinline__ uint32_t s2u(const void* p) {
    uint32_t a;
    asm("{ .reg .u64 t; cvta.to.shared.u64 t, %1; cvt.u32.u64 %0, t; }" : "=r"(a) : "l"(p));
    return a;
}
__device__ __forceinline__ uint32_t packh2(float v0, float v1) {
    __half2 h = __float22half2_rn(make_float2(v0, v1));
    return *(uint32_t*)&h;
}
__device__ __forceinline__ void mma16816(float* d, const uint32_t* a,
                                         uint32_t b0, uint32_t b1) {
    asm volatile(
        "mma.sync.aligned.m16n8k16.row.col.f32.f16.f16.f32 "
        "{%0,%1,%2,%3}, {%4,%5,%6,%7}, {%8,%9}, {%0,%1,%2,%3};"
        : "+f"(d[0]), "+f"(d[1]), "+f"(d[2]), "+f"(d[3])
        : "r"(a[0]), "r"(a[1]), "r"(a[2]), "r"(a[3]), "r"(b0), "r"(b1));
}
#define LDMX4(r0, r1, r2, r3, addr)                                           \
    asm volatile("ldmatrix.sync.aligned.m8n8.x4.shared.b16 {%0,%1,%2,%3}, [%4];" \
        : "=r"(r0), "=r"(r1), "=r"(r2), "=r"(r3) : "r"(addr))

// ---------------- weight prep: destination-major, coalesced writes ----------
// Fragment layout per 32-k tile: unit word widx = (((tile*2+ks)*16+np)*32+lane)*4+wsel
//   forward: lane=(n&7)*4+((kk&7)>>1), wsel=((kk>>3)<<1)|(nt&1), kk=k&15, nt=n>>3
__global__ void prep_weights(Params P)
{
    __half* gw = (__half*)g_w4;
    int wi = blockIdx.x * blockDim.x + threadIdx.x;   // dest word (fp16x2)
    if (wi >= WTOTAL / 2) return;
    int eb = wi * 2;                                   // fp16 elem offset
    int s, off;
    bool isw2;
    if      (eb < 32768)  { s = 0; isw2 = false; off = 0; }
    else if (eb < 98304)  { s = 0; isw2 = true;  off = 32768; }
    else if (eb < 163840) { s = 1; isw2 = false; off = 98304; }
    else if (eb < 229376) { s = 1; isw2 = true;  off = 163840; }
    else if (eb < 360448) { s = 2; isw2 = false; off = 229376; }
    else                  { s = 2; isw2 = true;  off = 360448; }
    const float* w = isw2 ? P.w2[s] : P.w1[s];
    int widx = (eb - off) >> 1;
    int wsel = widx & 3;
    int lane = (widx >> 2) & 31;
    int np   = (widx >> 7) & 15;
    int tks  = widx >> 11;
    int ks = tks & 1, tile = tks >> 1;
    int nt = np * 2 + (wsel & 1);
    int n  = nt * 8 + (lane >> 2);
    int k0 = tile * 32 + ks * 16 + ((wsel >> 1) << 3) + (lane & 3) * 2;
    float v0 = w[k0 * 256 + n];
    float v1 = w[(k0 + 1) * 256 + n];
    *(uint32_t*)(gw + eb) = packh2(v0, v1);
}

// ---------------- feat transpose: [C][HW] fp32 -> [HW][C] fp16 ---------------
__global__ void transpose_feat(const float* __restrict__ feat,
                               size_t toff, int C, int HW)
{
    __shared__ float tile[32][33];
    const int hw0 = blockIdx.x * 32;
    const int c0  = blockIdx.y * 32;
    const int b   = blockIdx.z;
    const int tx  = threadIdx.x & 31;
    const int ty  = threadIdx.x >> 5;

    const float* fb = feat + (size_t)b * C * HW;
#pragma unroll
    for (int j = 0; j < 4; j++) {
        int cc = c0 + ty + 8 * j;
        tile[ty + 8 * j][tx] = fb[(size_t)cc * HW + hw0 + tx];
    }
    __syncthreads();

    __half* thi = (__half*)g_t4 + toff;
    const int cp = threadIdx.x & 15;
    const int hb = threadIdx.x >> 4;
#pragma unroll
    for (int j = 0; j < 2; j++) {
        int hwl = hb + 16 * j;
        float v0 = tile[2 * cp][hwl];
        float v1 = tile[2 * cp + 1][hwl];
        size_t o = ((size_t)b * HW + hw0 + hwl) * C + c0 + 2 * cp;
        *(uint32_t*)(thi + o) = packh2(v0, v1);
    }
}

// ---------------- fused kernel: single-term fp16 MMA -------------------------
__global__ void __launch_bounds__(512, 1)
fused_mma(Params P)
{
    extern __shared__ uint32_t smw[];
    float*    sb1 = (float*)(smw + O_SB1);
    float*    sb2 = (float*)(smw + O_SB2);
    float*    ssp = (float*)(smw + O_SSP);
    int*      spid = (int*)(smw + O_PID);
    const uint32_t smb = s2u(smw);

    const int tid  = threadIdx.x;
    const int lane = tid & 31;
    const int wid  = tid >> 5;
    const int wm   = wid & 1;          // rows wm*32..+31
    const int wn   = wid >> 1;         // cols wn*32..+31
    const int gr   = lane >> 2;
    const int c    = lane & 3;
    const int lr   = lane & 15;
    const int lh   = lane >> 4;

    const int s  = blockIdx.x % 3;
    const int bi = blockIdx.x / 3;
    const int C  = 128 << s;
    const int HW = 32768 >> (2 * s);
    const int NT1 = C / KT;            // 4 / 8 / 16
    const int T   = NT1 + 8;

    const float* __restrict__ feat = P.feat[s];
    const int*   __restrict__ pid  = P.pid[s];

    const int row0 = bi * TM;
    const int b    = row0 >> 12;
    const int p0   = row0 & (PNUM - 1);

    if (tid < TM)  spid[tid] = pid[b * PNUM + p0 + tid];
    if (tid < 256) { sb1[tid] = __ldg(&P.b1[s][tid]); sb2[tid] = __ldg(&P.b2[s][tid]); }
    __syncthreads();

    const float* featb = feat + (size_t)b * C * HW;
    const __half* gw = (const __half*)g_w4;

    // s0 gather mapping
    const int gr0 = tid & 63;
    const int gkp = tid >> 6;
    const int mypid = spid[gr0];

    // s1/s2 coalesced A mapping: 8 threads/row, 8B chunks
    const int arow = tid >> 3;
    const int aq   = tid & 7;
    size_t abase = 0;
    if (s > 0)
        abase = TOFF(s) + ((size_t)b * HW + spid[arow]) * C;
    const __half* aplane = (const __half*)g_t4;

    float acc[2][4][4];
#pragma unroll
    for (int mt = 0; mt < 2; mt++)
#pragma unroll
        for (int nt = 0; nt < 4; nt++)
#pragma unroll
            for (int q = 0; q < 4; q++) acc[mt][nt][q] = 0.f;

    float va0, va1, va2, va3;
    uint2 pa;

    auto loadA = [&](int t) {
        if (s == 0) {
            int k = t * KT + gkp * 2;
            va0 = __ldg(&featb[(size_t)k * HW + mypid]);
            va1 = __ldg(&featb[(size_t)(k + 1) * HW + mypid]);
            int k2 = t * KT + (gkp + 8) * 2;
            va2 = __ldg(&featb[(size_t)k2 * HW + mypid]);
            va3 = __ldg(&featb[(size_t)(k2 + 1) * HW + mypid]);
        } else {
            pa = __ldg((const uint2*)(aplane + abase + t * KT) + aq);
        }
    };
    auto storeA = [&](int t) {
        uint32_t* axh = smw + O_SXA + (t & 1) * ABUF;
        if (s == 0) {
            axh[gr0 * 20 + gkp]     = packh2(va0, va1);
            axh[gr0 * 20 + gkp + 8] = packh2(va2, va3);
        } else {
            *(uint2*)&axh[arow * 20 + aq * 2] = pa;
        }
    };

    // ---- prologue: A tile 0 into buf0 ----
    loadA(0);
    storeA(0);
    __syncthreads();

    for (int t = 0; t < T; t++) {
        // ---- GEMM1->GEMM2 boundary: write h, sync before GEMM2 LDSM reads ----
        if (t == NT1) {
            uint32_t* shh = smw + O_SHH;
#pragma unroll
            for (int mt = 0; mt < 2; mt++) {
                const int rH = wm * 32 + mt * 16 + gr;
#pragma unroll
                for (int nt = 0; nt < 4; nt++) {
                    const int n  = wn * 32 + nt * 8 + 2 * c;
                    const int wi = wn * 16 + nt * 4 + c;
                    float v0 = fmaxf(acc[mt][nt][0] + sb1[n],     0.f);
                    float v1 = fmaxf(acc[mt][nt][1] + sb1[n + 1], 0.f);
                    float v2 = fmaxf(acc[mt][nt][2] + sb1[n],     0.f);
                    float v3 = fmaxf(acc[mt][nt][3] + sb1[n + 1], 0.f);
                    shh[rH * 132 + wi]       = packh2(v0, v1);
                    shh[(rH + 8) * 132 + wi] = packh2(v2, v3);
#pragma unroll
                    for (int q = 0; q < 4; q++) acc[mt][nt][q] = 0.f;
                }
            }
            __syncthreads();
        }

        // ---- prefetch A(t+1) into registers ----
        if (t + 1 < NT1) loadA(t + 1);

        // ---- B fragment pointer for this tile (gmem, L2-hot) ----
        const int woff = (t < NT1) ? (W1OFF(s) + t * 8192)
                                   : (W2OFF(s) + (t - NT1) * 8192);
        const uint4* fbt = (const uint4*)(gw + woff) + wn * 64 + lane;

        // ---- MMA phase ----
        const uint32_t bsel = (uint32_t)(t & 1);
#pragma unroll
        for (int ks = 0; ks < 2; ks++) {
            uint32_t ah0[4], ah1[4];
            if (t < NT1) {
                const uint32_t base = smb +
                    (O_SXA + bsel * ABUF + (wm * 32 + lr) * 20 + ks * 8 + lh * 4) * 4;
                LDMX4(ah0[0], ah0[1], ah0[2], ah0[3], base);
                LDMX4(ah1[0], ah1[1], ah1[2], ah1[3], base + 16 * 20 * 4);
            } else {
                const uint32_t base = smb +
                    (O_SHH + (wm * 32 + lr) * 132 + (t - NT1) * 16 + ks * 8 + lh * 4) * 4;
                LDMX4(ah0[0], ah0[1], ah0[2], ah0[3], base);
                LDMX4(ah1[0], ah1[1], ah1[2], ah1[3], base + 16 * 132 * 4);
            }
#pragma unroll
            for (int p = 0; p < 2; p++) {
                uint4 bh = __ldg(&fbt[ks * 512 + p * 32]);
                mma16816(acc[0][2 * p],     ah0, bh.x, bh.z);
                mma16816(acc[0][2 * p + 1], ah0, bh.y, bh.w);
                mma16816(acc[1][2 * p],     ah1, bh.x, bh.z);
                mma16816(acc[1][2 * p + 1], ah1, bh.y, bh.w);
            }
        }

        // ---- store prefetched A into the idle buffer; sync only in GEMM1 ----
        if (t + 1 < NT1) storeA(t + 1);
        if (t < NT1) __syncthreads();
    }

    // ================= epilogue: +b2, L2 normalize, store =================
#pragma unroll
    for (int mt = 0; mt < 2; mt++) {
        float ss0 = 0.f, ss1 = 0.f;
#pragma unroll
        for (int nt = 0; nt < 4; nt++) {
            const int n = wn * 32 + nt * 8 + 2 * c;
            acc[mt][nt][0] += sb2[n];
            acc[mt][nt][1] += sb2[n + 1];
            acc[mt][nt][2] += sb2[n];
            acc[mt][nt][3] += sb2[n + 1];
            ss0 = fmaf(acc[mt][nt][0], acc[mt][nt][0],
                  fmaf(acc[mt][nt][1], acc[mt][nt][1], ss0));
            ss1 = fmaf(acc[mt][nt][2], acc[mt][nt][2],
                  fmaf(acc[mt][nt][3], acc[mt][nt][3], ss1));
        }
        ss0 += __shfl_xor_sync(0xffffffffu, ss0, 1);
        ss0 += __shfl_xor_sync(0xffffffffu, ss0, 2);
        ss1 += __shfl_xor_sync(0xffffffffu, ss1, 1);
        ss1 += __shfl_xor_sync(0xffffffffu, ss1, 2);
        if (c == 0) {
            const int rE = wm * 32 + mt * 16 + gr;
            ssp[rE * 8 + wn]       = ss0;
            ssp[(rE + 8) * 8 + wn] = ss1;
        }
    }
    __syncthreads();

    float* __restrict__ out = P.out + ((size_t)s * ROWS + row0) * NCOL;
#pragma unroll
    for (int mt = 0; mt < 2; mt++) {
        const int rE = wm * 32 + mt * 16 + gr;
        float s0a = 0.f, s1a = 0.f;
#pragma unroll
        for (int j = 0; j < 8; j++) {
            s0a += ssp[rE * 8 + j];
            s1a += ssp[(rE + 8) * 8 + j];
        }
        const float inv0 = 1.f / (sqrtf(s0a) + 1e-7f);
        const float inv1 = 1.f / (sqrtf(s1a) + 1e-7f);
#pragma unroll
        for (int nt = 0; nt < 4; nt++) {
            const int n = wn * 32 + nt * 8 + 2 * c;
            float2 o0 = make_float2(acc[mt][nt][0] * inv0, acc[mt][nt][1] * inv0);
            float2 o1 = make_float2(acc[mt][nt][2] * inv1, acc[mt][nt][3] * inv1);
            *(float2*)&out[(size_t)rE * NCOL + n]       = o0;
            *(float2*)&out[(size_t)(rE + 8) * NCOL + n] = o1;
        }
    }
}

// ---------------- launch ----------------
extern "C" void kernel_launch(void* const* d_in, const int* in_sizes, int n_in,
                              void* d_out, int out_size)
{
    const bool sig_order = (n_in > 1) && (in_sizes[1] == 16777216);

    Params P;
    if (sig_order) {
        for (int s = 0; s < 3; s++) {
            P.feat[s] = (const float*)d_in[s];
            P.pid[s]  = (const int*)  d_in[3 + s];
            P.w1[s]   = (const float*)d_in[6 + 4 * s];
            P.b1[s]   = (const float*)d_in[7 + 4 * s];
            P.w2[s]   = (const float*)d_in[8 + 4 * s];
            P.b2[s]   = (const float*)d_in[9 + 4 * s];
        }
    } else {
        for (int s = 0; s < 3; s++) {
            P.feat[s] = (const float*)d_in[6 * s + 0];
            P.pid[s]  = (const int*)  d_in[6 * s + 1];
            P.w1[s]   = (const float*)d_in[6 * s + 2];
            P.b1[s]   = (const float*)d_in[6 * s + 3];
            P.w2[s]   = (const float*)d_in[6 * s + 4];
            P.b2[s]   = (const float*)d_in[6 * s + 5];
        }
    }
    P.out = (float*)d_out;

    cudaFuncSetAttribute(fused_mma, cudaFuncAttributeMaxDynamicSharedMemorySize,
                         SMEM_BYTES);

    prep_weights<<<(WTOTAL / 2 + 255) / 256, 256>>>(P);
    transpose_feat<<<dim3(8192 / 32, 256 / 32, 8), 256>>>(P.feat[1], TOFF(1), 256, 8192);
    transpose_feat<<<dim3(2048 / 32, 512 / 32, 8), 256>>>(P.feat[2], TOFF(2), 512, 2048);
    fused_mma<<<3 * (ROWS / TM), 512, SMEM_BYTES>>>(P);
}

// round 15
// speedup vs baseline: 2.6775x; 1.0376x over previous
#include <cuda_runtime.h>
#include <cuda_fp16.h>
#include <math.h>
#include <stdint.h>

// ---------------- problem constants ----------------
constexpr int NCOL = 256;
constexpr int PNUM = 4096;
constexpr int ROWS = 32768;
constexpr int TM   = 64;
constexpr int KT   = 32;

__host__ __device__ constexpr int W1OFF(int s) {
    return s == 0 ? 0 : (s == 1 ? 98304 : 229376);
}
__host__ __device__ constexpr int W2OFF(int s) {
    return s == 0 ? 32768 : (s == 1 ? 163840 : 360448);
}
constexpr int WTOTAL = 425984;

__host__ __device__ constexpr size_t TOFF(int s) {
    return s == 1 ? 0 : 16777216;
}
constexpr size_t TTOTAL = 25165824;

__device__ uint4 g_w4[WTOTAL / 8];    // W fp16, FRAGMENT layout
__device__ uint4 g_t4[TTOTAL / 8];    // feat^T fp16 (s1, s2)

// ---------------- smem word offsets ----------------
constexpr int O_SHH = 0;          // h: 64 x 132 words (fp16x2)
constexpr int O_SXA = 8448;       // A bufs: 2 x 1280 (64 rows x 20 words)
constexpr int ABUF  = 1280;
constexpr int O_SB1 = 11008;
constexpr int O_SB2 = 11264;
constexpr int O_SSP = 11520;      // 64 rows x 8 wn
constexpr int O_PID = 12032;
constexpr int SMEM_WORDS = 12096;
constexpr int SMEM_BYTES = SMEM_WORDS * 4;   // 48,384 B

struct Params {
    const float* feat[3];
    const int*   pid[3];
    const float* w1[3];
    const float* b1[3];
    const float* w2[3];
    const float* b2[3];
    float*       out;
};

__device__ __forceinline__ uint32_t s2u(const void* p) {
    uint32_t a;
    asm("{ .reg .u64 t; cvta.to.shared.u64 t, %1; cvt.u32.u64 %0, t; }" : "=r"(a) : "l"(p));
    return a;
}
__device__ __forceinline__ uint32_t packh2(float v0, float v1) {
    __half2 h = __float22half2_rn(make_float2(v0, v1));
    return *(uint32_t*)&h;
}
__device__ __forceinline__ void mma16816(float* d, const uint32_t* a,
                                         uint32_t b0, uint32_t b1) {
    asm volatile(
        "mma.sync.aligned.m16n8k16.row.col.f32.f16.f16.f32 "
        "{%0,%1,%2,%3}, {%4,%5,%6,%7}, {%8,%9}, {%0,%1,%2,%3};"
        : "+f"(d[0]), "+f"(d[1]), "+f"(d[2]), "+f"(d[3])
        : "r"(a[0]), "r"(a[1]), "r"(a[2]), "r"(a[3]), "r"(b0), "r"(b1));
}
#define LDMX4(r0, r1, r2, r3, addr)                                           \
    asm volatile("ldmatrix.sync.aligned.m8n8.x4.shared.b16 {%0,%1,%2,%3}, [%4];" \
        : "=r"(r0), "=r"(r1), "=r"(r2), "=r"(r3) : "r"(addr))

// ---------------- weight prep: destination-major, coalesced writes ----------
__global__ void prep_weights(Params P)
{
    __half* gw = (__half*)g_w4;
    int wi = blockIdx.x * blockDim.x + threadIdx.x;   // dest word (fp16x2)
    if (wi >= WTOTAL / 2) return;
    int eb = wi * 2;                                   // fp16 elem offset
    int s, off;
    bool isw2;
    if      (eb < 32768)  { s = 0; isw2 = false; off = 0; }
    else if (eb < 98304)  { s = 0; isw2 = true;  off = 32768; }
    else if (eb < 163840) { s = 1; isw2 = false; off = 98304; }
    else if (eb < 229376) { s = 1; isw2 = true;  off = 163840; }
    else if (eb < 360448) { s = 2; isw2 = false; off = 229376; }
    else                  { s = 2; isw2 = true;  off = 360448; }
    const float* w = isw2 ? P.w2[s] : P.w1[s];
    int widx = (eb - off) >> 1;
    int wsel = widx & 3;
    int lane = (widx >> 2) & 31;
    int np   = (widx >> 7) & 15;
    int tks  = widx >> 11;
    int ks = tks & 1, tile = tks >> 1;
    int nt = np * 2 + (wsel & 1);
    int n  = nt * 8 + (lane >> 2);
    int k0 = tile * 32 + ks * 16 + ((wsel >> 1) << 3) + (lane & 3) * 2;
    float v0 = w[k0 * 256 + n];
    float v1 = w[(k0 + 1) * 256 + n];
    *(uint32_t*)(gw + eb) = packh2(v0, v1);
}

// ---------------- feat transpose: [C][HW] fp32 -> [HW][C] fp16 ---------------
__global__ void transpose_feat(const float* __restrict__ feat,
                               size_t toff, int C, int HW)
{
    __shared__ float tile[32][33];
    const int hw0 = blockIdx.x * 32;
    const int c0  = blockIdx.y * 32;
    const int b   = blockIdx.z;
    const int tx  = threadIdx.x & 31;
    const int ty  = threadIdx.x >> 5;

    const float* fb = feat + (size_t)b * C * HW;
#pragma unroll
    for (int j = 0; j < 4; j++) {
        int cc = c0 + ty + 8 * j;
        tile[ty + 8 * j][tx] = fb[(size_t)cc * HW + hw0 + tx];
    }
    __syncthreads();

    __half* thi = (__half*)g_t4 + toff;
    const int cp = threadIdx.x & 15;
    const int hb = threadIdx.x >> 4;
#pragma unroll
    for (int j = 0; j < 2; j++) {
        int hwl = hb + 16 * j;
        float v0 = tile[2 * cp][hwl];
        float v1 = tile[2 * cp + 1][hwl];
        size_t o = ((size_t)b * HW + hw0 + hwl) * C + c0 + 2 * cp;
        *(uint32_t*)(thi + o) = packh2(v0, v1);
    }
}

// ---------------- fused kernel: fp16 MMA, reg-dbuf A and B -------------------
__global__ void __launch_bounds__(512, 1)
fused_mma(Params P)
{
    extern __shared__ uint32_t smw[];
    float*    sb1 = (float*)(smw + O_SB1);
    float*    sb2 = (float*)(smw + O_SB2);
    float*    ssp = (float*)(smw + O_SSP);
    int*      spid = (int*)(smw + O_PID);
    const uint32_t smb = s2u(smw);

    const int tid  = threadIdx.x;
    const int lane = tid & 31;
    const int wid  = tid >> 5;
    const int wm   = wid & 1;          // rows wm*32..+31
    const int wn   = wid >> 1;         // cols wn*32..+31
    const int gr   = lane >> 2;
    const int c    = lane & 3;
    const int lr   = lane & 15;
    const int lh   = lane >> 4;

    const int s  = blockIdx.x % 3;
    const int bi = blockIdx.x / 3;
    const int C  = 128 << s;
    const int HW = 32768 >> (2 * s);
    const int NT1 = C / KT;            // 4 / 8 / 16
    const int T   = NT1 + 8;

    const float* __restrict__ feat = P.feat[s];
    const int*   __restrict__ pid  = P.pid[s];

    const int row0 = bi * TM;
    const int b    = row0 >> 12;
    const int p0   = row0 & (PNUM - 1);

    if (tid < TM)  spid[tid] = pid[b * PNUM + p0 + tid];
    if (tid < 256) { sb1[tid] = __ldg(&P.b1[s][tid]); sb2[tid] = __ldg(&P.b2[s][tid]); }
    __syncthreads();

    const float* featb = feat + (size_t)b * C * HW;
    const __half* gw = (const __half*)g_w4;

    // s0 gather mapping
    const int gr0 = tid & 63;
    const int gkp = tid >> 6;
    const int mypid = spid[gr0];

    // s1/s2 coalesced A mapping: 8 threads/row, 8B chunks
    const int arow = tid >> 3;
    const int aq   = tid & 7;
    size_t abase = 0;
    if (s > 0)
        abase = TOFF(s) + ((size_t)b * HW + spid[arow]) * C;
    const __half* aplane = (const __half*)g_t4;

    float acc[2][4][4];
#pragma unroll
    for (int mt = 0; mt < 2; mt++)
#pragma unroll
        for (int nt = 0; nt < 4; nt++)
#pragma unroll
            for (int q = 0; q < 4; q++) acc[mt][nt][q] = 0.f;

    float va0, va1, va2, va3;
    uint2 pa;
    uint4 pb0, pb1, pb2, pb3;          // B fragment prefetch (next tile)

    auto loadA = [&](int t) {
        if (s == 0) {
            int k = t * KT + gkp * 2;
            va0 = __ldg(&featb[(size_t)k * HW + mypid]);
            va1 = __ldg(&featb[(size_t)(k + 1) * HW + mypid]);
            int k2 = t * KT + (gkp + 8) * 2;
            va2 = __ldg(&featb[(size_t)k2 * HW + mypid]);
            va3 = __ldg(&featb[(size_t)(k2 + 1) * HW + mypid]);
        } else {
            pa = __ldg((const uint2*)(aplane + abase + t * KT) + aq);
        }
    };
    auto storeA = [&](int t) {
        uint32_t* axh = smw + O_SXA + (t & 1) * ABUF;
        if (s == 0) {
            axh[gr0 * 20 + gkp]     = packh2(va0, va1);
            axh[gr0 * 20 + gkp + 8] = packh2(va2, va3);
        } else {
            *(uint2*)&axh[arow * 20 + aq * 2] = pa;
        }
    };
    auto loadB = [&](int t) {
        const int woff = (t < NT1) ? (W1OFF(s) + t * 8192)
                                   : (W2OFF(s) + (t - NT1) * 8192);
        const uint4* fbt = (const uint4*)(gw + woff) + wn * 64 + lane;
        pb0 = __ldg(&fbt[0]);      // ks0 p0
        pb1 = __ldg(&fbt[32]);     // ks0 p1
        pb2 = __ldg(&fbt[512]);    // ks1 p0
        pb3 = __ldg(&fbt[544]);    // ks1 p1
    };

    // ---- prologue: tile 0 ----
    loadB(0);
    loadA(0);
    storeA(0);
    __syncthreads();

    for (int t = 0; t < T; t++) {
        // ---- GEMM1->GEMM2 boundary: write h, sync before GEMM2 LDSM reads ----
        if (t == NT1) {
            uint32_t* shh = smw + O_SHH;
#pragma unroll
            for (int mt = 0; mt < 2; mt++) {
                const int rH = wm * 32 + mt * 16 + gr;
#pragma unroll
                for (int nt = 0; nt < 4; nt++) {
                    const int n  = wn * 32 + nt * 8 + 2 * c;
                    const int wi = wn * 16 + nt * 4 + c;
                    float v0 = fmaxf(acc[mt][nt][0] + sb1[n],     0.f);
                    float v1 = fmaxf(acc[mt][nt][1] + sb1[n + 1], 0.f);
                    float v2 = fmaxf(acc[mt][nt][2] + sb1[n],     0.f);
                    float v3 = fmaxf(acc[mt][nt][3] + sb1[n + 1], 0.f);
                    shh[rH * 132 + wi]       = packh2(v0, v1);
                    shh[(rH + 8) * 132 + wi] = packh2(v2, v3);
#pragma unroll
                    for (int q = 0; q < 4; q++) acc[mt][nt][q] = 0.f;
                }
            }
            __syncthreads();
        }

        // ---- consume current B fragments; start loads for tile t+1 ----
        uint4 cb0 = pb0, cb1 = pb1, cb2 = pb2, cb3 = pb3;
        if (t + 1 < T)   loadB(t + 1);
        if (t + 1 < NT1) loadA(t + 1);

        // ---- MMA phase ----
        const uint32_t bsel = (uint32_t)(t & 1);
#pragma unroll
        for (int ks = 0; ks < 2; ks++) {
            uint32_t ah0[4], ah1[4];
            if (t < NT1) {
                const uint32_t base = smb +
                    (O_SXA + bsel * ABUF + (wm * 32 + lr) * 20 + ks * 8 + lh * 4) * 4;
                LDMX4(ah0[0], ah0[1], ah0[2], ah0[3], base);
                LDMX4(ah1[0], ah1[1], ah1[2], ah1[3], base + 16 * 20 * 4);
            } else {
                const uint32_t base = smb +
                    (O_SHH + (wm * 32 + lr) * 132 + (t - NT1) * 16 + ks * 8 + lh * 4) * 4;
                LDMX4(ah0[0], ah0[1], ah0[2], ah0[3], base);
                LDMX4(ah1[0], ah1[1], ah1[2], ah1[3], base + 16 * 132 * 4);
            }
            const uint4 bA = ks ? cb2 : cb0;
            const uint4 bB = ks ? cb3 : cb1;
            mma16816(acc[0][0], ah0, bA.x, bA.z);
            mma16816(acc[0][1], ah0, bA.y, bA.w);
            mma16816(acc[1][0], ah1, bA.x, bA.z);
            mma16816(acc[1][1], ah1, bA.y, bA.w);
            mma16816(acc[0][2], ah0, bB.x, bB.z);
            mma16816(acc[0][3], ah0, bB.y, bB.w);
            mma16816(acc[1][2], ah1, bB.x, bB.z);
            mma16816(acc[1][3], ah1, bB.y, bB.w);
        }

        // ---- store prefetched A into the idle buffer; sync only in GEMM1 ----
        if (t + 1 < NT1) storeA(t + 1);
        if (t < NT1) __syncthreads();
    }

    // ================= epilogue: +b2, L2 normalize, store =================
#pragma unroll
    for (int mt = 0; mt < 2; mt++) {
        float ss0 = 0.f, ss1 = 0.f;
#pragma unroll
        for (int nt = 0; nt < 4; nt++) {
            const int n = wn * 32 + nt * 8 + 2 * c;
            acc[mt][nt][0] += sb2[n];
            acc[mt][nt][1] += sb2[n + 1];
            acc[mt][nt][2] += sb2[n];
            acc[mt][nt][3] += sb2[n + 1];
            ss0 = fmaf(acc[mt][nt][0], acc[mt][nt][0],
                  fmaf(acc[mt][nt][1], acc[mt][nt][1], ss0));
            ss1 = fmaf(acc[mt][nt][2], acc[mt][nt][2],
                  fmaf(acc[mt][nt][3], acc[mt][nt][3], ss1));
        }
        ss0 += __shfl_xor_sync(0xffffffffu, ss0, 1);
        ss0 += __shfl_xor_sync(0xffffffffu, ss0, 2);
        ss1 += __shfl_xor_sync(0xffffffffu, ss1, 1);
        ss1 += __shfl_xor_sync(0xffffffffu, ss1, 2);
        if (c == 0) {
            const int rE = wm * 32 + mt * 16 + gr;
            ssp[rE * 8 + wn]       = ss0;
            ssp[(rE + 8) * 8 + wn] = ss1;
        }
    }
    __syncthreads();

    float* __restrict__ out = P.out + ((size_t)s * ROWS + row0) * NCOL;
#pragma unroll
    for (int mt = 0; mt < 2; mt++) {
        const int rE = wm * 32 + mt * 16 + gr;
        float s0a = 0.f, s1a = 0.f;
#pragma unroll
        for (int j = 0; j < 8; j++) {
            s0a += ssp[rE * 8 + j];
            s1a += ssp[(rE + 8) * 8 + j];
        }
        const float inv0 = 1.f / (sqrtf(s0a) + 1e-7f);
        const float inv1 = 1.f / (sqrtf(s1a) + 1e-7f);
#pragma unroll
        for (int nt = 0; nt < 4; nt++) {
            const int n = wn * 32 + nt * 8 + 2 * c;
            float2 o0 = make_float2(acc[mt][nt][0] * inv0, acc[mt][nt][1] * inv0);
            float2 o1 = make_float2(acc[mt][nt][2] * inv1, acc[mt][nt][3] * inv1);
            *(float2*)&out[(size_t)rE * NCOL + n]       = o0;
            *(float2*)&out[(size_t)(rE + 8) * NCOL + n] = o1;
        }
    }
}

// ---------------- launch ----------------
extern "C" void kernel_launch(void* const* d_in, const int* in_sizes, int n_in,
                              void* d_out, int out_size)
{
    const bool sig_order = (n_in > 1) && (in_sizes[1] == 16777216);

    Params P;
    if (sig_order) {
        for (int s = 0; s < 3; s++) {
            P.feat[s] = (const float*)d_in[s];
            P.pid[s]  = (const int*)  d_in[3 + s];
            P.w1[s]   = (const float*)d_in[6 + 4 * s];
            P.b1[s]   = (const float*)d_in[7 + 4 * s];
            P.w2[s]   = (const float*)d_in[8 + 4 * s];
            P.b2[s]   = (const float*)d_in[9 + 4 * s];
        }
    } else {
        for (int s = 0; s < 3; s++) {
            P.feat[s] = (const float*)d_in[6 * s + 0];
            P.pid[s]  = (const int*)  d_in[6 * s + 1];
            P.w1[s]   = (const float*)d_in[6 * s + 2];
            P.b1[s]   = (const float*)d_in[6 * s + 3];
            P.w2[s]   = (const float*)d_in[6 * s + 4];
            P.b2[s]   = (const float*)d_in[6 * s + 5];
        }
    }
    P.out = (float*)d_out;

    cudaFuncSetAttribute(fused_mma, cudaFuncAttributeMaxDynamicSharedMemorySize,
                         SMEM_BYTES);

    prep_weights<<<(WTOTAL / 2 + 255) / 256, 256>>>(P);
    transpose_feat<<<dim3(8192 / 32, 256 / 32, 8), 256>>>(P.feat[1], TOFF(1), 256, 8192);
    transpose_feat<<<dim3(2048 / 32, 512 / 32, 8), 256>>>(P.feat[2], TOFF(2), 512, 2048);
    fused_mma<<<3 * (ROWS / TM), 512, SMEM_BYTES>>>(P);
}

// round 16
// speedup vs baseline: 2.8890x; 1.0790x over previous
#include <cuda_runtime.h>
#include <cuda_fp16.h>
#include <math.h>
#include <stdint.h>

// ---------------- problem constants ----------------
constexpr int NCOL = 256;
constexpr int PNUM = 4096;
constexpr int ROWS = 32768;
constexpr int TM   = 64;
constexpr int KT   = 32;

__host__ __device__ constexpr int W1OFF(int s) {
    return s == 0 ? 0 : (s == 1 ? 98304 : 229376);
}
__host__ __device__ constexpr int W2OFF(int s) {
    return s == 0 ? 32768 : (s == 1 ? 163840 : 360448);
}
constexpr int WTOTAL = 425984;

__host__ __device__ constexpr size_t TOFF(int s) {
    return s == 1 ? 0 : 16777216;
}
constexpr size_t TTOTAL = 25165824;

__device__ uint4 g_w4[WTOTAL / 8];    // W fp16, FRAGMENT layout
__device__ uint4 g_t4[TTOTAL / 8];    // feat^T fp16 (s1, s2)

// ---------------- smem word offsets ----------------
constexpr int O_SHH = 0;          // h: 64 x 132 words (fp16x2)
constexpr int O_SXA = 8448;       // A bufs: 2 x 1280 (64 rows x 20 words)
constexpr int ABUF  = 1280;
constexpr int O_SB1 = 11008;
constexpr int O_SB2 = 11264;
constexpr int O_SSP = 11520;      // 64 rows x 8 wn
constexpr int O_PID = 12032;
constexpr int SMEM_WORDS = 12096;
constexpr int SMEM_BYTES = SMEM_WORDS * 4;   // 48,384 B

struct Params {
    const float* feat[3];
    const int*   pid[3];
    const float* w1[3];
    const float* b1[3];
    const float* w2[3];
    const float* b2[3];
    float*       out;
};

__device__ __forceinline__ uint32_t s2u(const void* p) {
    uint32_t a;
    asm("{ .reg .u64 t; cvta.to.shared.u64 t, %1; cvt.u32.u64 %0, t; }" : "=r"(a) : "l"(p));
    return a;
}
__device__ __forceinline__ uint32_t packh2(float v0, float v1) {
    __half2 h = __float22half2_rn(make_float2(v0, v1));
    return *(uint32_t*)&h;
}
__device__ __forceinline__ void mma16816(float* d, const uint32_t* a,
                                         uint32_t b0, uint32_t b1) {
    asm volatile(
        "mma.sync.aligned.m16n8k16.row.col.f32.f16.f16.f32 "
        "{%0,%1,%2,%3}, {%4,%5,%6,%7}, {%8,%9}, {%0,%1,%2,%3};"
        : "+f"(d[0]), "+f"(d[1]), "+f"(d[2]), "+f"(d[3])
        : "r"(a[0]), "r"(a[1]), "r"(a[2]), "r"(a[3]), "r"(b0), "r"(b1));
}
#define LDMX4(r0, r1, r2, r3, addr)                                           \
    asm volatile("ldmatrix.sync.aligned.m8n8.x4.shared.b16 {%0,%1,%2,%3}, [%4];" \
        : "=r"(r0), "=r"(r1), "=r"(r2), "=r"(r3) : "r"(addr))

// ---------------- weight prep: destination-major, coalesced writes ----------
__global__ void prep_weights(Params P)
{
    __half* gw = (__half*)g_w4;
    int wi = blockIdx.x * blockDim.x + threadIdx.x;   // dest word (fp16x2)
    if (wi >= WTOTAL / 2) return;
    int eb = wi * 2;                                   // fp16 elem offset
    int s, off;
    bool isw2;
    if      (eb < 32768)  { s = 0; isw2 = false; off = 0; }
    else if (eb < 98304)  { s = 0; isw2 = true;  off = 32768; }
    else if (eb < 163840) { s = 1; isw2 = false; off = 98304; }
    else if (eb < 229376) { s = 1; isw2 = true;  off = 163840; }
    else if (eb < 360448) { s = 2; isw2 = false; off = 229376; }
    else                  { s = 2; isw2 = true;  off = 360448; }
    const float* w = isw2 ? P.w2[s] : P.w1[s];
    int widx = (eb - off) >> 1;
    int wsel = widx & 3;
    int lane = (widx >> 2) & 31;
    int np   = (widx >> 7) & 15;
    int tks  = widx >> 11;
    int ks = tks & 1, tile = tks >> 1;
    int nt = np * 2 + (wsel & 1);
    int n  = nt * 8 + (lane >> 2);
    int k0 = tile * 32 + ks * 16 + ((wsel >> 1) << 3) + (lane & 3) * 2;
    float v0 = w[k0 * 256 + n];
    float v1 = w[(k0 + 1) * 256 + n];
    *(uint32_t*)(gw + eb) = packh2(v0, v1);
}

// ---------------- feat transpose: [C][HW] fp32 -> [HW][C] fp16 ---------------
__global__ void transpose_feat(const float* __restrict__ feat,
                               size_t toff, int C, int HW)
{
    __shared__ float tile[32][33];
    const int hw0 = blockIdx.x * 32;
    const int c0  = blockIdx.y * 32;
    const int b   = blockIdx.z;
    const int tx  = threadIdx.x & 31;
    const int ty  = threadIdx.x >> 5;

    const float* fb = feat + (size_t)b * C * HW;
#pragma unroll
    for (int j = 0; j < 4; j++) {
        int cc = c0 + ty + 8 * j;
        tile[ty + 8 * j][tx] = fb[(size_t)cc * HW + hw0 + tx];
    }
    __syncthreads();

    __half* thi = (__half*)g_t4 + toff;
    const int cp = threadIdx.x & 15;
    const int hb = threadIdx.x >> 4;
#pragma unroll
    for (int j = 0; j < 2; j++) {
        int hwl = hb + 16 * j;
        float v0 = tile[2 * cp][hwl];
        float v1 = tile[2 * cp + 1][hwl];
        size_t o = ((size_t)b * HW + hw0 + hwl) * C + c0 + 2 * cp;
        *(uint32_t*)(thi + o) = packh2(v0, v1);
    }
}

// ---------------- fused kernel: lean two-phase loop -------------------------
__global__ void __launch_bounds__(512, 1)
fused_mma(Params P)
{
    extern __shared__ uint32_t smw[];
    float*    sb1 = (float*)(smw + O_SB1);
    float*    sb2 = (float*)(smw + O_SB2);
    float*    ssp = (float*)(smw + O_SSP);
    int*      spid = (int*)(smw + O_PID);
    const uint32_t smb = s2u(smw);

    const int tid  = threadIdx.x;
    const int lane = tid & 31;
    const int wid  = tid >> 5;
    const int wm   = wid & 1;          // rows wm*32..+31
    const int wn   = wid >> 1;         // cols wn*32..+31
    const int gr   = lane >> 2;
    const int c    = lane & 3;
    const int lr   = lane & 15;
    const int lh   = lane >> 4;

    const int s  = blockIdx.x % 3;
    const int bi = blockIdx.x / 3;
    const int C  = 128 << s;
    const int HW = 32768 >> (2 * s);
    const int NT1 = C / KT;            // 4 / 8 / 16

    const float* __restrict__ feat = P.feat[s];
    const int*   __restrict__ pid  = P.pid[s];

    const int row0 = bi * TM;
    const int b    = row0 >> 12;
    const int p0   = row0 & (PNUM - 1);

    if (tid < TM)  spid[tid] = pid[b * PNUM + p0 + tid];
    if (tid < 256) { sb1[tid] = __ldg(&P.b1[s][tid]); sb2[tid] = __ldg(&P.b2[s][tid]); }
    __syncthreads();

    const float* featb = feat + (size_t)b * C * HW;
    const __half* gw = (const __half*)g_w4;

    // s0 gather mapping (running offsets; no per-tile multiplies)
    const int gr0 = tid & 63;
    const int gkp = tid >> 6;
    const int mypid = spid[gr0];
    size_t f0 = (size_t)(gkp * 2) * HW + mypid;
    size_t f1 = (size_t)((gkp + 8) * 2) * HW + mypid;
    const size_t ASTEP = (size_t)KT * HW;

    // s1/s2 coalesced A mapping (running pointer)
    const int arow = tid >> 3;
    const int aq   = tid & 7;
    const uint2* ap = nullptr;
    if (s > 0)
        ap = (const uint2*)((const __half*)g_t4 + TOFF(s) +
                            ((size_t)b * HW + spid[arow]) * C) + aq;

    float acc[2][4][4];
#pragma unroll
    for (int mt = 0; mt < 2; mt++)
#pragma unroll
        for (int nt = 0; nt < 4; nt++)
#pragma unroll
            for (int q = 0; q < 4; q++) acc[mt][nt][q] = 0.f;

    float va0, va1, va2, va3;
    uint2 pa;
    uint4 pb0, pb1, pb2, pb3;

    // hoisted addresses
    const uint32_t adrA1 = smb + (O_SXA + (wm * 32 + lr) * 20 + lh * 4) * 4;  // buf0
    const uint32_t adrA2 = smb + (O_SHH + (wm * 32 + lr) * 132 + lh * 4) * 4;
    const uint32_t ABUF4 = ABUF * 4;

    // B fragment running pointer (advance 1024 uint4 per tile)
    const uint4* fb_cur = (const uint4*)(gw + W1OFF(s)) + wn * 64 + lane;
    const uint4* const fb_w2 = (const uint4*)(gw + W2OFF(s)) + wn * 64 + lane;

    auto loadA = [&]() {
        if (s == 0) {
            va0 = __ldg(&featb[f0]);
            va1 = __ldg(&featb[f0 + HW]);
            va2 = __ldg(&featb[f1]);
            va3 = __ldg(&featb[f1 + HW]);
            f0 += ASTEP; f1 += ASTEP;
        } else {
            pa = __ldg(ap);
            ap += 8;
        }
    };
    auto storeA = [&](int buf) {
        uint32_t* axh = smw + O_SXA + buf * ABUF;
        if (s == 0) {
            axh[gr0 * 20 + gkp]     = packh2(va0, va1);
            axh[gr0 * 20 + gkp + 8] = packh2(va2, va3);
        } else {
            *(uint2*)&axh[arow * 20 + aq * 2] = pa;
        }
    };
    auto loadB = [&]() {
        pb0 = __ldg(fb_cur);
        pb1 = __ldg(fb_cur + 32);
        pb2 = __ldg(fb_cur + 512);
        pb3 = __ldg(fb_cur + 544);
    };

    // ---- prologue: tile 0 ----
    loadB();
    loadA();
    storeA(0);
    __syncthreads();

    // ================= GEMM1 loop =================
    for (int t = 0; t < NT1; t++) {
        uint4 cb0 = pb0, cb1 = pb1, cb2 = pb2, cb3 = pb3;
        const bool more1 = (t + 1 < NT1);
        fb_cur = more1 ? (fb_cur + 1024) : fb_w2;
        loadB();                       // B for tile t+1 (w1 next or w2 tile 0)
        if (more1) loadA();

        const uint32_t adrA = adrA1 + (uint32_t)(t & 1) * ABUF4;
#pragma unroll
        for (int ks = 0; ks < 2; ks++) {
            uint32_t ah0[4], ah1[4];
            LDMX4(ah0[0], ah0[1], ah0[2], ah0[3], adrA + ks * 32);
            LDMX4(ah1[0], ah1[1], ah1[2], ah1[3], adrA + ks * 32 + 1280);
            const uint4 bA = ks ? cb2 : cb0;
            const uint4 bB = ks ? cb3 : cb1;
            mma16816(acc[0][0], ah0, bA.x, bA.z);
            mma16816(acc[0][1], ah0, bA.y, bA.w);
            mma16816(acc[1][0], ah1, bA.x, bA.z);
            mma16816(acc[1][1], ah1, bA.y, bA.w);
            mma16816(acc[0][2], ah0, bB.x, bB.z);
            mma16816(acc[0][3], ah0, bB.y, bB.w);
            mma16816(acc[1][2], ah1, bB.x, bB.z);
            mma16816(acc[1][3], ah1, bB.y, bB.w);
        }
        if (more1) storeA((t + 1) & 1);
        __syncthreads();
    }

    // ---- h epilogue: +b1, relu, pack fp16, write h; sync ----
    {
        uint32_t* shh = smw + O_SHH;
#pragma unroll
        for (int mt = 0; mt < 2; mt++) {
            const int rH = wm * 32 + mt * 16 + gr;
#pragma unroll
            for (int nt = 0; nt < 4; nt++) {
                const int n  = wn * 32 + nt * 8 + 2 * c;
                const int wi = wn * 16 + nt * 4 + c;
                float v0 = fmaxf(acc[mt][nt][0] + sb1[n],     0.f);
                float v1 = fmaxf(acc[mt][nt][1] + sb1[n + 1], 0.f);
                float v2 = fmaxf(acc[mt][nt][2] + sb1[n],     0.f);
                float v3 = fmaxf(acc[mt][nt][3] + sb1[n + 1], 0.f);
                shh[rH * 132 + wi]       = packh2(v0, v1);
                shh[(rH + 8) * 132 + wi] = packh2(v2, v3);
#pragma unroll
                for (int q = 0; q < 4; q++) acc[mt][nt][q] = 0.f;
            }
        }
        __syncthreads();
    }

    // ================= GEMM2 loop (barrier-free) =================
#pragma unroll 2
    for (int tt = 0; tt < 8; tt++) {
        uint4 cb0 = pb0, cb1 = pb1, cb2 = pb2, cb3 = pb3;
        if (tt < 7) { fb_cur += 1024; loadB(); }

        const uint32_t adrA = adrA2 + (uint32_t)tt * 64;
#pragma unroll
        for (int ks = 0; ks < 2; ks++) {
            uint32_t ah0[4], ah1[4];
            LDMX4(ah0[0], ah0[1], ah0[2], ah0[3], adrA + ks * 32);
            LDMX4(ah1[0], ah1[1], ah1[2], ah1[3], adrA + ks * 32 + 16 * 132 * 4);
            const uint4 bA = ks ? cb2 : cb0;
            const uint4 bB = ks ? cb3 : cb1;
            mma16816(acc[0][0], ah0, bA.x, bA.z);
            mma16816(acc[0][1], ah0, bA.y, bA.w);
            mma16816(acc[1][0], ah1, bA.x, bA.z);
            mma16816(acc[1][1], ah1, bA.y, bA.w);
            mma16816(acc[0][2], ah0, bB.x, bB.z);
            mma16816(acc[0][3], ah0, bB.y, bB.w);
            mma16816(acc[1][2], ah1, bB.x, bB.z);
            mma16816(acc[1][3], ah1, bB.y, bB.w);
        }
    }

    // ================= epilogue: +b2, L2 normalize, store =================
#pragma unroll
    for (int mt = 0; mt < 2; mt++) {
        float ss0 = 0.f, ss1 = 0.f;
#pragma unroll
        for (int nt = 0; nt < 4; nt++) {
            const int n = wn * 32 + nt * 8 + 2 * c;
            acc[mt][nt][0] += sb2[n];
            acc[mt][nt][1] += sb2[n + 1];
            acc[mt][nt][2] += sb2[n];
            acc[mt][nt][3] += sb2[n + 1];
            ss0 = fmaf(acc[mt][nt][0], acc[mt][nt][0],
                  fmaf(acc[mt][nt][1], acc[mt][nt][1], ss0));
            ss1 = fmaf(acc[mt][nt][2], acc[mt][nt][2],
                  fmaf(acc[mt][nt][3], acc[mt][nt][3], ss1));
        }
        ss0 += __shfl_xor_sync(0xffffffffu, ss0, 1);
        ss0 += __shfl_xor_sync(0xffffffffu, ss0, 2);
        ss1 += __shfl_xor_sync(0xffffffffu, ss1, 1);
        ss1 += __shfl_xor_sync(0xffffffffu, ss1, 2);
        if (c == 0) {
            const int rE = wm * 32 + mt * 16 + gr;
            ssp[rE * 8 + wn]       = ss0;
            ssp[(rE + 8) * 8 + wn] = ss1;
        }
    }
    __syncthreads();

    float* __restrict__ out = P.out + ((size_t)s * ROWS + row0) * NCOL;
#pragma unroll
    for (int mt = 0; mt < 2; mt++) {
        const int rE = wm * 32 + mt * 16 + gr;
        float s0a = 0.f, s1a = 0.f;
#pragma unroll
        for (int j = 0; j < 8; j++) {
            s0a += ssp[rE * 8 + j];
            s1a += ssp[(rE + 8) * 8 + j];
        }
        const float inv0 = 1.f / (sqrtf(s0a) + 1e-7f);
        const float inv1 = 1.f / (sqrtf(s1a) + 1e-7f);
#pragma unroll
        for (int nt = 0; nt < 4; nt++) {
            const int n = wn * 32 + nt * 8 + 2 * c;
            float2 o0 = make_float2(acc[mt][nt][0] * inv0, acc[mt][nt][1] * inv0);
            float2 o1 = make_float2(acc[mt][nt][2] * inv1, acc[mt][nt][3] * inv1);
            *(float2*)&out[(size_t)rE * NCOL + n]       = o0;
            *(float2*)&out[(size_t)(rE + 8) * NCOL + n] = o1;
        }
    }
}

// ---------------- launch ----------------
extern "C" void kernel_launch(void* const* d_in, const int* in_sizes, int n_in,
                              void* d_out, int out_size)
{
    const bool sig_order = (n_in > 1) && (in_sizes[1] == 16777216);

    Params P;
    if (sig_order) {
        for (int s = 0; s < 3; s++) {
            P.feat[s] = (const float*)d_in[s];
            P.pid[s]  = (const int*)  d_in[3 + s];
            P.w1[s]   = (const float*)d_in[6 + 4 * s];
            P.b1[s]   = (const float*)d_in[7 + 4 * s];
            P.w2[s]   = (const float*)d_in[8 + 4 * s];
            P.b2[s]   = (const float*)d_in[9 + 4 * s];
        }
    } else {
        for (int s = 0; s < 3; s++) {
            P.feat[s] = (const float*)d_in[6 * s + 0];
            P.pid[s]  = (const int*)  d_in[6 * s + 1];
            P.w1[s]   = (const float*)d_in[6 * s + 2];
            P.b1[s]   = (const float*)d_in[6 * s + 3];
            P.w2[s]   = (const float*)d_in[6 * s + 4];
            P.b2[s]   = (const float*)d_in[6 * s + 5];
        }
    }
    P.out = (float*)d_out;

    cudaFuncSetAttribute(fused_mma, cudaFuncAttributeMaxDynamicSharedMemorySize,
                         SMEM_BYTES);

    prep_weights<<<(WTOTAL / 2 + 255) / 256, 256>>>(P);
    transpose_feat<<<dim3(8192 / 32, 256 / 32, 8), 256>>>(P.feat[1], TOFF(1), 256, 8192);
    transpose_feat<<<dim3(2048 / 32, 512 / 32, 8), 256>>>(P.feat[2], TOFF(2), 512, 2048);
    fused_mma<<<3 * (ROWS / TM), 512, SMEM_BYTES>>>(P);
}

// round 17
// speedup vs baseline: 3.0965x; 1.0718x over previous
#include <cuda_runtime.h>
#include <cuda_fp16.h>
#include <math.h>
#include <stdint.h>

// ---------------- problem constants ----------------
constexpr int NCOL = 256;
constexpr int PNUM = 4096;
constexpr int ROWS = 32768;
constexpr int TM   = 32;      // M rows per CTA (halved; 2 CTAs/SM)
constexpr int KT   = 32;

__host__ __device__ constexpr int W1OFF(int s) {
    return s == 0 ? 0 : (s == 1 ? 98304 : 229376);
}
__host__ __device__ constexpr int W2OFF(int s) {
    return s == 0 ? 32768 : (s == 1 ? 163840 : 360448);
}
constexpr int WTOTAL = 425984;

__host__ __device__ constexpr size_t TOFF(int s) {
    return s == 1 ? 0 : 16777216;
}
constexpr size_t TTOTAL = 25165824;

__device__ uint4 g_w4[WTOTAL / 8];    // W fp16, FRAGMENT layout
__device__ uint4 g_t4[TTOTAL / 8];    // feat^T fp16 (s1, s2)

// ---------------- smem word offsets ----------------
constexpr int O_SHH = 0;          // h: 32 x 132 words (fp16x2)
constexpr int O_SXA = 4224;       // A bufs: 2 x 640 (32 rows x 20 words)
constexpr int ABUF  = 640;
constexpr int O_SB1 = 5504;
constexpr int O_SB2 = 5760;
constexpr int O_SSP = 6016;       // 32 rows x 8 wn
constexpr int O_PID = 6272;
constexpr int SMEM_WORDS = 6304;
constexpr int SMEM_BYTES = SMEM_WORDS * 4;   // 25,216 B (2 CTAs/SM easily)

struct Params {
    const float* feat[3];
    const int*   pid[3];
    const float* w1[3];
    const float* b1[3];
    const float* w2[3];
    const float* b2[3];
    float*       out;
};

__device__ __forceinline__ uint32_t s2u(const void* p) {
    uint32_t a;
    asm("{ .reg .u64 t; cvta.to.shared.u64 t, %1; cvt.u32.u64 %0, t; }" : "=r"(a) : "l"(p));
    return a;
}
__device__ __forceinline__ uint32_t packh2(float v0, float v1) {
    __half2 h = __float22half2_rn(make_float2(v0, v1));
    return *(uint32_t*)&h;
}
__device__ __forceinline__ void mma16816(float* d, const uint32_t* a,
                                         uint32_t b0, uint32_t b1) {
    asm volatile(
        "mma.sync.aligned.m16n8k16.row.col.f32.f16.f16.f32 "
        "{%0,%1,%2,%3}, {%4,%5,%6,%7}, {%8,%9}, {%0,%1,%2,%3};"
        : "+f"(d[0]), "+f"(d[1]), "+f"(d[2]), "+f"(d[3])
        : "r"(a[0]), "r"(a[1]), "r"(a[2]), "r"(a[3]), "r"(b0), "r"(b1));
}
#define LDMX4(r0, r1, r2, r3, addr)                                           \
    asm volatile("ldmatrix.sync.aligned.m8n8.x4.shared.b16 {%0,%1,%2,%3}, [%4];" \
        : "=r"(r0), "=r"(r1), "=r"(r2), "=r"(r3) : "r"(addr))

// ---------------- weight prep: destination-major, coalesced writes ----------
__global__ void prep_weights(Params P)
{
    __half* gw = (__half*)g_w4;
    int wi = blockIdx.x * blockDim.x + threadIdx.x;   // dest word (fp16x2)
    if (wi >= WTOTAL / 2) return;
    int eb = wi * 2;                                   // fp16 elem offset
    int s, off;
    bool isw2;
    if      (eb < 32768)  { s = 0; isw2 = false; off = 0; }
    else if (eb < 98304)  { s = 0; isw2 = true;  off = 32768; }
    else if (eb < 163840) { s = 1; isw2 = false; off = 98304; }
    else if (eb < 229376) { s = 1; isw2 = true;  off = 163840; }
    else if (eb < 360448) { s = 2; isw2 = false; off = 229376; }
    else                  { s = 2; isw2 = true;  off = 360448; }
    const float* w = isw2 ? P.w2[s] : P.w1[s];
    int widx = (eb - off) >> 1;
    int wsel = widx & 3;
    int lane = (widx >> 2) & 31;
    int np   = (widx >> 7) & 15;
    int tks  = widx >> 11;
    int ks = tks & 1, tile = tks >> 1;
    int nt = np * 2 + (wsel & 1);
    int n  = nt * 8 + (lane >> 2);
    int k0 = tile * 32 + ks * 16 + ((wsel >> 1) << 3) + (lane & 3) * 2;
    float v0 = w[k0 * 256 + n];
    float v1 = w[(k0 + 1) * 256 + n];
    *(uint32_t*)(gw + eb) = packh2(v0, v1);
}

// ---------------- feat transpose: [C][HW] fp32 -> [HW][C] fp16 ---------------
__global__ void transpose_feat(const float* __restrict__ feat,
                               size_t toff, int C, int HW)
{
    __shared__ float tile[32][33];
    const int hw0 = blockIdx.x * 32;
    const int c0  = blockIdx.y * 32;
    const int b   = blockIdx.z;
    const int tx  = threadIdx.x & 31;
    const int ty  = threadIdx.x >> 5;

    const float* fb = feat + (size_t)b * C * HW;
#pragma unroll
    for (int j = 0; j < 4; j++) {
        int cc = c0 + ty + 8 * j;
        tile[ty + 8 * j][tx] = fb[(size_t)cc * HW + hw0 + tx];
    }
    __syncthreads();

    __half* thi = (__half*)g_t4 + toff;
    const int cp = threadIdx.x & 15;
    const int hb = threadIdx.x >> 4;
#pragma unroll
    for (int j = 0; j < 2; j++) {
        int hwl = hb + 16 * j;
        float v0 = tile[2 * cp][hwl];
        float v1 = tile[2 * cp + 1][hwl];
        size_t o = ((size_t)b * HW + hw0 + hwl) * C + c0 + 2 * cp;
        *(uint32_t*)(thi + o) = packh2(v0, v1);
    }
}

// ---------------- fused kernel: 256 thr, 2 CTAs/SM --------------------------
__global__ void __launch_bounds__(256, 2)
fused_mma(Params P)
{
    extern __shared__ uint32_t smw[];
    float*    sb1 = (float*)(smw + O_SB1);
    float*    sb2 = (float*)(smw + O_SB2);
    float*    ssp = (float*)(smw + O_SSP);
    int*      spid = (int*)(smw + O_PID);
    const uint32_t smb = s2u(smw);

    const int tid  = threadIdx.x;
    const int lane = tid & 31;
    const int wn   = tid >> 5;         // warp = n-group: cols wn*32..+31
    const int gr   = lane >> 2;
    const int c    = lane & 3;
    const int lr   = lane & 15;
    const int lh   = lane >> 4;

    const int s  = blockIdx.x % 3;
    const int bi = blockIdx.x / 3;
    const int C  = 128 << s;
    const int HW = 32768 >> (2 * s);
    const int NT1 = C / KT;            // 4 / 8 / 16

    const float* __restrict__ feat = P.feat[s];
    const int*   __restrict__ pid  = P.pid[s];

    const int row0 = bi * TM;
    const int b    = row0 >> 12;
    const int p0   = row0 & (PNUM - 1);

    if (tid < TM)  spid[tid] = pid[b * PNUM + p0 + tid];
    sb1[tid] = __ldg(&P.b1[s][tid]);
    sb2[tid] = __ldg(&P.b2[s][tid]);
    __syncthreads();

    const float* featb = feat + (size_t)b * C * HW;
    const __half* gw = (const __half*)g_w4;

    // s0 gather mapping (running offsets)
    const int gr0 = tid & 31;          // row 0..31
    const int gkp = tid >> 5;          // 0..7
    const int mypid = spid[gr0];
    size_t f0 = (size_t)(gkp * 2) * HW + mypid;
    size_t f1 = (size_t)((gkp + 8) * 2) * HW + mypid;
    const size_t ASTEP = (size_t)KT * HW;

    // s1/s2 coalesced A mapping (running pointer)
    const int arow = tid >> 3;         // 0..31
    const int aq   = tid & 7;
    const uint2* ap = nullptr;
    if (s > 0)
        ap = (const uint2*)((const __half*)g_t4 + TOFF(s) +
                            ((size_t)b * HW + spid[arow]) * C) + aq;

    float acc[2][4][4];
#pragma unroll
    for (int mt = 0; mt < 2; mt++)
#pragma unroll
        for (int nt = 0; nt < 4; nt++)
#pragma unroll
            for (int q = 0; q < 4; q++) acc[mt][nt][q] = 0.f;

    float va0, va1, va2, va3;
    uint2 pa;
    uint4 pb0, pb1, pb2, pb3;

    // hoisted smem addresses
    const uint32_t adrA1 = smb + (O_SXA + lr * 20 + lh * 4) * 4;   // buf0, rows 0-15
    const uint32_t adrA2 = smb + (O_SHH + lr * 132 + lh * 4) * 4;
    const uint32_t ABUF4 = ABUF * 4;

    // B fragment running pointer (advance 1024 uint4 per tile)
    const uint4* fb_cur = (const uint4*)(gw + W1OFF(s)) + wn * 64 + lane;
    const uint4* const fb_w2 = (const uint4*)(gw + W2OFF(s)) + wn * 64 + lane;

    auto loadA = [&]() {
        if (s == 0) {
            va0 = __ldg(&featb[f0]);
            va1 = __ldg(&featb[f0 + HW]);
            va2 = __ldg(&featb[f1]);
            va3 = __ldg(&featb[f1 + HW]);
            f0 += ASTEP; f1 += ASTEP;
        } else {
            pa = __ldg(ap);
            ap += 8;
        }
    };
    auto storeA = [&](int buf) {
        uint32_t* axh = smw + O_SXA + buf * ABUF;
        if (s == 0) {
            axh[gr0 * 20 + gkp]     = packh2(va0, va1);
            axh[gr0 * 20 + gkp + 8] = packh2(va2, va3);
        } else {
            *(uint2*)&axh[arow * 20 + aq * 2] = pa;
        }
    };
    auto loadB = [&]() {
        pb0 = __ldg(fb_cur);
        pb1 = __ldg(fb_cur + 32);
        pb2 = __ldg(fb_cur + 512);
        pb3 = __ldg(fb_cur + 544);
    };

    // ---- prologue: tile 0 ----
    loadB();
    loadA();
    storeA(0);
    __syncthreads();

    // ================= GEMM1 loop =================
    for (int t = 0; t < NT1; t++) {
        uint4 cb0 = pb0, cb1 = pb1, cb2 = pb2, cb3 = pb3;
        const bool more1 = (t + 1 < NT1);
        fb_cur = more1 ? (fb_cur + 1024) : fb_w2;
        loadB();                       // B for tile t+1 (w1 next or w2 tile 0)
        if (more1) loadA();

        const uint32_t adrA = adrA1 + (uint32_t)(t & 1) * ABUF4;
#pragma unroll
        for (int ks = 0; ks < 2; ks++) {
            uint32_t ah0[4], ah1[4];
            LDMX4(ah0[0], ah0[1], ah0[2], ah0[3], adrA + ks * 32);
            LDMX4(ah1[0], ah1[1], ah1[2], ah1[3], adrA + ks * 32 + 16 * 20 * 4);
            const uint4 bA = ks ? cb2 : cb0;
            const uint4 bB = ks ? cb3 : cb1;
            mma16816(acc[0][0], ah0, bA.x, bA.z);
            mma16816(acc[0][1], ah0, bA.y, bA.w);
            mma16816(acc[1][0], ah1, bA.x, bA.z);
            mma16816(acc[1][1], ah1, bA.y, bA.w);
            mma16816(acc[0][2], ah0, bB.x, bB.z);
            mma16816(acc[0][3], ah0, bB.y, bB.w);
            mma16816(acc[1][2], ah1, bB.x, bB.z);
            mma16816(acc[1][3], ah1, bB.y, bB.w);
        }
        if (more1) storeA((t + 1) & 1);
        __syncthreads();
    }

    // ---- h epilogue: +b1, relu, pack fp16, write h; sync ----
    {
        uint32_t* shh = smw + O_SHH;
#pragma unroll
        for (int mt = 0; mt < 2; mt++) {
            const int rH = mt * 16 + gr;
#pragma unroll
            for (int nt = 0; nt < 4; nt++) {
                const int n  = wn * 32 + nt * 8 + 2 * c;
                const int wi = wn * 16 + nt * 4 + c;
                float v0 = fmaxf(acc[mt][nt][0] + sb1[n],     0.f);
                float v1 = fmaxf(acc[mt][nt][1] + sb1[n + 1], 0.f);
                float v2 = fmaxf(acc[mt][nt][2] + sb1[n],     0.f);
                float v3 = fmaxf(acc[mt][nt][3] + sb1[n + 1], 0.f);
                shh[rH * 132 + wi]       = packh2(v0, v1);
                shh[(rH + 8) * 132 + wi] = packh2(v2, v3);
#pragma unroll
                for (int q = 0; q < 4; q++) acc[mt][nt][q] = 0.f;
            }
        }
        __syncthreads();
    }

    // ================= GEMM2 loop (barrier-free) =================
#pragma unroll 2
    for (int tt = 0; tt < 8; tt++) {
        uint4 cb0 = pb0, cb1 = pb1, cb2 = pb2, cb3 = pb3;
        if (tt < 7) { fb_cur += 1024; loadB(); }

        const uint32_t adrA = adrA2 + (uint32_t)tt * 64;
#pragma unroll
        for (int ks = 0; ks < 2; ks++) {
            uint32_t ah0[4], ah1[4];
            LDMX4(ah0[0], ah0[1], ah0[2], ah0[3], adrA + ks * 32);
            LDMX4(ah1[0], ah1[1], ah1[2], ah1[3], adrA + ks * 32 + 16 * 132 * 4);
            const uint4 bA = ks ? cb2 : cb0;
            const uint4 bB = ks ? cb3 : cb1;
            mma16816(acc[0][0], ah0, bA.x, bA.z);
            mma16816(acc[0][1], ah0, bA.y, bA.w);
            mma16816(acc[1][0], ah1, bA.x, bA.z);
            mma16816(acc[1][1], ah1, bA.y, bA.w);
            mma16816(acc[0][2], ah0, bB.x, bB.z);
            mma16816(acc[0][3], ah0, bB.y, bB.w);
            mma16816(acc[1][2], ah1, bB.x, bB.z);
            mma16816(acc[1][3], ah1, bB.y, bB.w);
        }
    }

    // ================= epilogue: +b2, L2 normalize, store =================
#pragma unroll
    for (int mt = 0; mt < 2; mt++) {
        float ss0 = 0.f, ss1 = 0.f;
#pragma unroll
        for (int nt = 0; nt < 4; nt++) {
            const int n = wn * 32 + nt * 8 + 2 * c;
            acc[mt][nt][0] += sb2[n];
            acc[mt][nt][1] += sb2[n + 1];
            acc[mt][nt][2] += sb2[n];
            acc[mt][nt][3] += sb2[n + 1];
            ss0 = fmaf(acc[mt][nt][0], acc[mt][nt][0],
                  fmaf(acc[mt][nt][1], acc[mt][nt][1], ss0));
            ss1 = fmaf(acc[mt][nt][2], acc[mt][nt][2],
                  fmaf(acc[mt][nt][3], acc[mt][nt][3], ss1));
        }
        ss0 += __shfl_xor_sync(0xffffffffu, ss0, 1);
        ss0 += __shfl_xor_sync(0xffffffffu, ss0, 2);
        ss1 += __shfl_xor_sync(0xffffffffu, ss1, 1);
        ss1 += __shfl_xor_sync(0xffffffffu, ss1, 2);
        if (c == 0) {
            const int rE = mt * 16 + gr;
            ssp[rE * 8 + wn]       = ss0;
            ssp[(rE + 8) * 8 + wn] = ss1;
        }
    }
    __syncthreads();

    float* __restrict__ out = P.out + ((size_t)s * ROWS + row0) * NCOL;
#pragma unroll
    for (int mt = 0; mt < 2; mt++) {
        const int rE = mt * 16 + gr;
        float s0a = 0.f, s1a = 0.f;
#pragma unroll
        for (int j = 0; j < 8; j++) {
            s0a += ssp[rE * 8 + j];
            s1a += ssp[(rE + 8) * 8 + j];
        }
        const float inv0 = 1.f / (sqrtf(s0a) + 1e-7f);
        const float inv1 = 1.f / (sqrtf(s1a) + 1e-7f);
#pragma unroll
        for (int nt = 0; nt < 4; nt++) {
            const int n = wn * 32 + nt * 8 + 2 * c;
            float2 o0 = make_float2(acc[mt][nt][0] * inv0, acc[mt][nt][1] * inv0);
            float2 o1 = make_float2(acc[mt][nt][2] * inv1, acc[mt][nt][3] * inv1);
            *(float2*)&out[(size_t)rE * NCOL + n]       = o0;
            *(float2*)&out[(size_t)(rE + 8) * NCOL + n] = o1;
        }
    }
}

// ---------------- launch ----------------
extern "C" void kernel_launch(void* const* d_in, const int* in_sizes, int n_in,
                              void* d_out, int out_size)
{
    const bool sig_order = (n_in > 1) && (in_sizes[1] == 16777216);

    Params P;
    if (sig_order) {
        for (int s = 0; s < 3; s++) {
            P.feat[s] = (const float*)d_in[s];
            P.pid[s]  = (const int*)  d_in[3 + s];
            P.w1[s]   = (const float*)d_in[6 + 4 * s];
            P.b1[s]   = (const float*)d_in[7 + 4 * s];
            P.w2[s]   = (const float*)d_in[8 + 4 * s];
            P.b2[s]   = (const float*)d_in[9 + 4 * s];
        }
    } else {
        for (int s = 0; s < 3; s++) {
            P.feat[s] = (const float*)d_in[6 * s + 0];
            P.pid[s]  = (const int*)  d_in[6 * s + 1];
            P.w1[s]   = (const float*)d_in[6 * s + 2];
            P.b1[s]   = (const float*)d_in[6 * s + 3];
            P.w2[s]   = (const float*)d_in[6 * s + 4];
            P.b2[s]   = (const float*)d_in[6 * s + 5];
        }
    }
    P.out = (float*)d_out;

    prep_weights<<<(WTOTAL / 2 + 255) / 256, 256>>>(P);
    transpose_feat<<<dim3(8192 / 32, 256 / 32, 8), 256>>>(P.feat[1], TOFF(1), 256, 8192);
    transpose_feat<<<dim3(2048 / 32, 512 / 32, 8), 256>>>(P.feat[2], TOFF(2), 512, 2048);
    fused_mma<<<3 * (ROWS / TM), 256, SMEM_BYTES>>>(P);
}